// round 6
// baseline (speedup 1.0000x reference)
#include <cuda_runtime.h>
#include <cuda_bf16.h>
#include <math.h>
#include <stdint.h>

#define NMAX 50048
#define EMAX 800000

// Scratch (device globals: no allocation allowed)
__device__ float g_h1pre[NMAX * 64];
__device__ float g_h1[NMAX * 64];
__device__ float g_hd[NMAX * 64];
__device__ float g_a2[NMAX * 64];
__device__ float g_dinv[NMAX];
__device__ int   g_cnt[NMAX];
__device__ int   g_cur[NMAX];
__device__ int   g_off[NMAX + 1];
__device__ int2  g_edge[EMAX];     // (src, bits(dinv[s]*dinv[d])) sorted by dst
// bf16 split weights: W1T = W_enc_gnn^T [64 n][256 k], W2T = W_dec_gnn^T [256 n][64 k]
__device__ __nv_bfloat16 g_w1t_hi[64 * 256];
__device__ __nv_bfloat16 g_w1t_lo[64 * 256];
__device__ __nv_bfloat16 g_w2t_hi[256 * 64];
__device__ __nv_bfloat16 g_w2t_lo[256 * 64];

__device__ __forceinline__ uint32_t pack2bf(float a, float b) {
    __nv_bfloat162 t = __floats2bfloat162_rn(a, b);
    return *(uint32_t*)&t;
}
__device__ __forceinline__ float bf_hi_f(float a) {
    return __bfloat162float(__float2bfloat16_rn(a));
}
__device__ __forceinline__ uint32_t prmt7632(uint32_t a, uint32_t b) {
    uint32_t r;
    asm("prmt.b32 %0, %1, %2, 0x7632;" : "=r"(r) : "r"(a), "r"(b));
    return r;
}
// truncation hi/lo split of 8 fp32 -> bf16 hi pack + bf16 lo pack
__device__ __forceinline__ void split8(const float4 f0, const float4 f1,
                                       uint4 &hv, uint4 &lv) {
    uint32_t u0 = __float_as_uint(f0.x), u1 = __float_as_uint(f0.y);
    uint32_t u2 = __float_as_uint(f0.z), u3 = __float_as_uint(f0.w);
    uint32_t u4 = __float_as_uint(f1.x), u5 = __float_as_uint(f1.y);
    uint32_t u6 = __float_as_uint(f1.z), u7 = __float_as_uint(f1.w);
    hv = make_uint4(prmt7632(u0, u1), prmt7632(u2, u3),
                    prmt7632(u4, u5), prmt7632(u6, u7));
    float l0 = f0.x - __uint_as_float(u0 & 0xFFFF0000u);
    float l1 = f0.y - __uint_as_float(u1 & 0xFFFF0000u);
    float l2 = f0.z - __uint_as_float(u2 & 0xFFFF0000u);
    float l3 = f0.w - __uint_as_float(u3 & 0xFFFF0000u);
    float l4 = f1.x - __uint_as_float(u4 & 0xFFFF0000u);
    float l5 = f1.y - __uint_as_float(u5 & 0xFFFF0000u);
    float l6 = f1.z - __uint_as_float(u6 & 0xFFFF0000u);
    float l7 = f1.w - __uint_as_float(u7 & 0xFFFF0000u);
    lv = make_uint4(pack2bf(l0, l1), pack2bf(l2, l3),
                    pack2bf(l4, l5), pack2bf(l6, l7));
}

// mma.sync m16n8k16 bf16 -> f32 accum (portable PTX, lowers to HMMA)
__device__ __forceinline__ void mma16816(float* d, const uint32_t* a, const uint32_t* b) {
    asm volatile(
        "mma.sync.aligned.m16n8k16.row.col.f32.bf16.bf16.f32 "
        "{%0,%1,%2,%3}, {%4,%5,%6,%7}, {%8,%9}, {%0,%1,%2,%3};"
        : "+f"(d[0]), "+f"(d[1]), "+f"(d[2]), "+f"(d[3])
        : "r"(a[0]), "r"(a[1]), "r"(a[2]), "r"(a[3]), "r"(b[0]), "r"(b[1]));
}

// ---------------------------------------------------------------------------
// CSR build
// ---------------------------------------------------------------------------
__global__ void k_count(const int* __restrict__ dst, int E) {
    int e = blockIdx.x * blockDim.x + threadIdx.x;
    if (e < E) atomicAdd(&g_cnt[dst[e]], 1);
}

// single-block fused scan: offsets + dinv + cursor reset
__global__ void k_scan_all(int n, int E) {
    __shared__ int s[1024];
    const int per = (n + 1023) / 1024;
    int beg = threadIdx.x * per;
    int end = beg + per; if (end > n) end = n;
    int sum = 0;
    for (int i = beg; i < end; i++) sum += g_cnt[i];
    int v = sum;
    s[threadIdx.x] = v;
    __syncthreads();
    for (int st = 1; st < 1024; st <<= 1) {
        int t = (threadIdx.x >= st) ? s[threadIdx.x - st] : 0;
        __syncthreads();
        s[threadIdx.x] += t;
        __syncthreads();
    }
    int pre = s[threadIdx.x] - v;  // exclusive prefix of this chunk
    for (int i = beg; i < end; i++) {
        int c = g_cnt[i];
        g_off[i]  = pre;
        g_dinv[i] = rsqrtf(1.0f + (float)c);
        g_cur[i]  = 0;
        pre += c;
    }
    if (threadIdx.x == 0) g_off[n] = E;
}

__global__ void k_fill(const int* __restrict__ src, const int* __restrict__ dst, int E) {
    int e = blockIdx.x * blockDim.x + threadIdx.x;
    if (e < E) {
        int d = dst[e], si = src[e];
        int pos = g_off[d] + atomicAdd(&g_cur[d], 1);
        float w = g_dinv[si] * g_dinv[d];
        g_edge[pos] = make_int2(si, __float_as_int(w));
    }
}

// ---------------------------------------------------------------------------
// Weight transpose + bf16 hi/lo split (rn version; tiny, done once per call)
// ---------------------------------------------------------------------------
__global__ void k_wconv(const float* __restrict__ W1, const float* __restrict__ W2) {
    int i = blockIdx.x * blockDim.x + threadIdx.x;
    if (i < 64 * 256) {            // W1T[n][k] = W1[k][n]
        int n = i >> 8, k = i & 255;
        float v = W1[k * 64 + n];
        float h = bf_hi_f(v);
        g_w1t_hi[i] = __float2bfloat16_rn(h);
        g_w1t_lo[i] = __float2bfloat16_rn(v - h);
    } else if (i < 2 * 64 * 256) { // W2T[n][k] = W2[k][n]
        int t = i - 64 * 256;
        int n = t >> 6, k = t & 63;
        float v = W2[k * 256 + n];
        float h = bf_hi_f(v);
        g_w2t_hi[t] = __float2bfloat16_rn(h);
        g_w2t_lo[t] = __float2bfloat16_rn(v - h);
    }
}

// ---------------------------------------------------------------------------
// GEMM1 (mma.sync): [M,256]fp32 @ W1 -> [M,64]fp32, block = 128 rows x 64 cols
// ---------------------------------------------------------------------------
#define G1_LDA 72
#define G1_AH  0
#define G1_AL  (128 * 72)
#define G1_BH  (2 * 128 * 72)
#define G1_BL  (2 * 128 * 72 + 64 * 72)
#define G1_SMEM ((2 * 128 * 72 + 2 * 64 * 72) * 2)

__global__ void __launch_bounds__(256) k_mma_gemm1(
    const float* __restrict__ A, float* __restrict__ C, int M) {
    extern __shared__ __align__(16) uint16_t sm1[];
    const int tid = threadIdx.x;
    const int wid = tid >> 5, lane = tid & 31;
    const int g = lane >> 2, tig = lane & 3;
    const int rowBase = blockIdx.x * 128;
    const int warpRow = wid * 16;

    float acc[8][4];
#pragma unroll
    for (int i = 0; i < 8; i++)
#pragma unroll
        for (int j = 0; j < 4; j++) acc[i][j] = 0.0f;

    for (int kc0 = 0; kc0 < 256; kc0 += 64) {
#pragma unroll
        for (int i = 0; i < 4; i++) {
            int c = tid + i * 256;
            int r = c >> 3, k8 = (c & 7) * 8;
            int gr = rowBase + r;
            float4 f0, f1;
            if (gr < M) {
                f0 = *(const float4*)&A[(size_t)gr * 256 + kc0 + k8];
                f1 = *(const float4*)&A[(size_t)gr * 256 + kc0 + k8 + 4];
            } else { f0 = make_float4(0, 0, 0, 0); f1 = f0; }
            uint4 hv, lv;
            split8(f0, f1, hv, lv);
            *(uint4*)&sm1[G1_AH + r * G1_LDA + k8] = hv;
            *(uint4*)&sm1[G1_AL + r * G1_LDA + k8] = lv;
        }
#pragma unroll
        for (int i = 0; i < 2; i++) {
            int c = tid + i * 256;
            int n = c >> 3, k8 = (c & 7) * 8;
            *(uint4*)&sm1[G1_BH + n * G1_LDA + k8] = *(const uint4*)&g_w1t_hi[n * 256 + kc0 + k8];
            *(uint4*)&sm1[G1_BL + n * G1_LDA + k8] = *(const uint4*)&g_w1t_lo[n * 256 + kc0 + k8];
        }
        __syncthreads();
#pragma unroll
        for (int ks = 0; ks < 4; ks++) {
            int col0 = ks * 16 + 2 * tig;
            int col1 = col0 + 8;
            int row0 = warpRow + g, row1 = row0 + 8;
            uint32_t ah[4], al[4];
            ah[0] = *(uint32_t*)&sm1[G1_AH + row0 * G1_LDA + col0];
            ah[1] = *(uint32_t*)&sm1[G1_AH + row1 * G1_LDA + col0];
            ah[2] = *(uint32_t*)&sm1[G1_AH + row0 * G1_LDA + col1];
            ah[3] = *(uint32_t*)&sm1[G1_AH + row1 * G1_LDA + col1];
            al[0] = *(uint32_t*)&sm1[G1_AL + row0 * G1_LDA + col0];
            al[1] = *(uint32_t*)&sm1[G1_AL + row1 * G1_LDA + col0];
            al[2] = *(uint32_t*)&sm1[G1_AL + row0 * G1_LDA + col1];
            al[3] = *(uint32_t*)&sm1[G1_AL + row1 * G1_LDA + col1];
#pragma unroll
            for (int nt = 0; nt < 8; nt++) {
                int nr = nt * 8 + g;
                uint32_t bh[2], bl[2];
                bh[0] = *(uint32_t*)&sm1[G1_BH + nr * G1_LDA + col0];
                bh[1] = *(uint32_t*)&sm1[G1_BH + nr * G1_LDA + col1];
                bl[0] = *(uint32_t*)&sm1[G1_BL + nr * G1_LDA + col0];
                bl[1] = *(uint32_t*)&sm1[G1_BL + nr * G1_LDA + col1];
                mma16816(acc[nt], ah, bh);
                mma16816(acc[nt], ah, bl);
                mma16816(acc[nt], al, bh);
            }
        }
        __syncthreads();
    }
    int gr0 = rowBase + warpRow + g;
    int gr1 = gr0 + 8;
#pragma unroll
    for (int nt = 0; nt < 8; nt++) {
        int col = nt * 8 + 2 * tig;
        if (gr0 < M) *(float2*)&C[(size_t)gr0 * 64 + col] = make_float2(acc[nt][0], acc[nt][1]);
        if (gr1 < M) *(float2*)&C[(size_t)gr1 * 64 + col] = make_float2(acc[nt][2], acc[nt][3]);
    }
}

// ---------------------------------------------------------------------------
// GEMM2 (mma.sync): [M,64]fp32 @ W2 + bias -> [M,256]fp32
// block = 64 rows x 256 cols; warp = 16 rows x 128 cols
// ---------------------------------------------------------------------------
#define G2_LDA 72
#define G2_AH  0
#define G2_AL  (64 * 72)
#define G2_BH  (2 * 64 * 72)
#define G2_BL  (2 * 64 * 72 + 256 * 72)
#define G2_SMEM ((2 * 64 * 72 + 2 * 256 * 72) * 2)

__global__ void __launch_bounds__(256) k_mma_gemm2(
    const float* __restrict__ A, const float* __restrict__ bias,
    float* __restrict__ C, int M) {
    extern __shared__ __align__(16) uint16_t sm2[];
    const int tid = threadIdx.x;
    const int wid = tid >> 5, lane = tid & 31;
    const int g = lane >> 2, tig = lane & 3;
    const int rowBase = blockIdx.x * 64;
    const int warpRow = (wid & 3) * 16;
    const int warpCol = (wid >> 2) * 128;

#pragma unroll
    for (int i = 0; i < 2; i++) {
        int c = tid + i * 256;
        int r = c >> 3, k8 = (c & 7) * 8;
        int gr = rowBase + r;
        float4 f0, f1;
        if (gr < M) {
            f0 = *(const float4*)&A[(size_t)gr * 64 + k8];
            f1 = *(const float4*)&A[(size_t)gr * 64 + k8 + 4];
        } else { f0 = make_float4(0, 0, 0, 0); f1 = f0; }
        uint4 hv, lv;
        split8(f0, f1, hv, lv);
        *(uint4*)&sm2[G2_AH + r * G2_LDA + k8] = hv;
        *(uint4*)&sm2[G2_AL + r * G2_LDA + k8] = lv;
    }
#pragma unroll
    for (int i = 0; i < 8; i++) {
        int c = tid + i * 256;
        int n = c >> 3, k8 = (c & 7) * 8;
        *(uint4*)&sm2[G2_BH + n * G2_LDA + k8] = *(const uint4*)&g_w2t_hi[n * 64 + k8];
        *(uint4*)&sm2[G2_BL + n * G2_LDA + k8] = *(const uint4*)&g_w2t_lo[n * 64 + k8];
    }
    __syncthreads();

    float acc[16][4];
#pragma unroll
    for (int i = 0; i < 16; i++)
#pragma unroll
        for (int j = 0; j < 4; j++) acc[i][j] = 0.0f;

#pragma unroll
    for (int ks = 0; ks < 4; ks++) {
        int col0 = ks * 16 + 2 * tig;
        int col1 = col0 + 8;
        int row0 = warpRow + g, row1 = row0 + 8;
        uint32_t ah[4], al[4];
        ah[0] = *(uint32_t*)&sm2[G2_AH + row0 * G2_LDA + col0];
        ah[1] = *(uint32_t*)&sm2[G2_AH + row1 * G2_LDA + col0];
        ah[2] = *(uint32_t*)&sm2[G2_AH + row0 * G2_LDA + col1];
        ah[3] = *(uint32_t*)&sm2[G2_AH + row1 * G2_LDA + col1];
        al[0] = *(uint32_t*)&sm2[G2_AL + row0 * G2_LDA + col0];
        al[1] = *(uint32_t*)&sm2[G2_AL + row1 * G2_LDA + col0];
        al[2] = *(uint32_t*)&sm2[G2_AL + row0 * G2_LDA + col1];
        al[3] = *(uint32_t*)&sm2[G2_AL + row1 * G2_LDA + col1];
#pragma unroll
        for (int nt = 0; nt < 16; nt++) {
            int nr = warpCol + nt * 8 + g;
            uint32_t bh[2], bl[2];
            bh[0] = *(uint32_t*)&sm2[G2_BH + nr * G2_LDA + col0];
            bh[1] = *(uint32_t*)&sm2[G2_BH + nr * G2_LDA + col1];
            bl[0] = *(uint32_t*)&sm2[G2_BL + nr * G2_LDA + col0];
            bl[1] = *(uint32_t*)&sm2[G2_BL + nr * G2_LDA + col1];
            mma16816(acc[nt], ah, bh);
            mma16816(acc[nt], ah, bl);
            mma16816(acc[nt], al, bh);
        }
    }
    int gr0 = rowBase + warpRow + g;
    int gr1 = gr0 + 8;
#pragma unroll
    for (int nt = 0; nt < 16; nt++) {
        int col = warpCol + nt * 8 + 2 * tig;
        float2 bv = *(const float2*)&bias[col];
        if (gr0 < M)
            *(float2*)&C[(size_t)gr0 * 256 + col] = make_float2(acc[nt][0] + bv.x, acc[nt][1] + bv.y);
        if (gr1 < M)
            *(float2*)&C[(size_t)gr1 * 256 + col] = make_float2(acc[nt][2] + bv.x, acc[nt][3] + bv.y);
    }
}

// ---------------------------------------------------------------------------
// CSR aggregation (warp per node, float2 per lane, precomputed edge weights)
// ---------------------------------------------------------------------------
__global__ void k_agg64(const float* __restrict__ h,
                        const float* __restrict__ bias,
                        float* __restrict__ out, int n, int relu) {
    int node = blockIdx.x * 8 + (threadIdx.x >> 5);
    if (node >= n) return;
    int lane = threadIdx.x & 31;
    const float2* __restrict__ h2 = (const float2*)h;
    float dn = g_dinv[node];
    float2 self = h2[node * 32 + lane];
    float ax = self.x * dn * dn;
    float ay = self.y * dn * dn;
    int p = g_off[node], end = g_off[node + 1];
    for (; p + 3 < end; p += 4) {
        int2 e0 = g_edge[p],     e1 = g_edge[p + 1];
        int2 e2 = g_edge[p + 2], e3 = g_edge[p + 3];
        float2 v0 = h2[e0.x * 32 + lane];
        float2 v1 = h2[e1.x * 32 + lane];
        float2 v2 = h2[e2.x * 32 + lane];
        float2 v3 = h2[e3.x * 32 + lane];
        float w0 = __int_as_float(e0.y), w1 = __int_as_float(e1.y);
        float w2 = __int_as_float(e2.y), w3 = __int_as_float(e3.y);
        ax += v0.x * w0 + v1.x * w1 + v2.x * w2 + v3.x * w3;
        ay += v0.y * w0 + v1.y * w1 + v2.y * w2 + v3.y * w3;
    }
    for (; p < end; p++) {
        int2 e = g_edge[p];
        float w = __int_as_float(e.y);
        float2 v = h2[e.x * 32 + lane];
        ax += v.x * w;
        ay += v.y * w;
    }
    if (bias) {
        float2 b = ((const float2*)bias)[lane];
        ax += b.x; ay += b.y;
    }
    if (relu) { ax = fmaxf(ax, 0.0f); ay = fmaxf(ay, 0.0f); }
    ((float2*)out)[node * 32 + lane] = make_float2(ax, ay);
}

// ---------------------------------------------------------------------------
// Fused mid: z, hd, pred
// ---------------------------------------------------------------------------
__global__ void k_fused_mid(const float* __restrict__ h1,
                            const float* __restrict__ Wef, const float* __restrict__ bef,
                            const float* __restrict__ Wdf, const float* __restrict__ bdf,
                            const float* __restrict__ Wc,  const float* __restrict__ bc,
                            float* __restrict__ z_out, float* __restrict__ hd_out,
                            float* __restrict__ pred_out, int n) {
    __shared__ float sWef[64 * 32];
    __shared__ float sWdf[32 * 64];
    __shared__ float sWc[32 * 3];
    __shared__ float sbef[32], sbdf[64], sbc[3];
    __shared__ float sh[16][64];
    __shared__ float sz[16][32];
    int tid = threadIdx.x;  // 256
    for (int i = tid; i < 64 * 32; i += 256) sWef[i] = Wef[i];
    for (int i = tid; i < 32 * 64; i += 256) sWdf[i] = Wdf[i];
    for (int i = tid; i < 32 * 3; i += 256) sWc[i] = Wc[i];
    if (tid < 32) sbef[tid] = bef[tid];
    if (tid < 64) sbdf[tid] = bdf[tid];
    if (tid < 3)  sbc[tid]  = bc[tid];
    int rowBase = blockIdx.x * 16;
    for (int i = tid; i < 16 * 64; i += 256) {
        int r = i >> 6, c = i & 63;
        int gr = rowBase + r;
        sh[r][c] = (gr < n) ? h1[gr * 64 + c] : 0.0f;
    }
    __syncthreads();
    for (int o = tid; o < 512; o += 256) {
        int r = o >> 5, j = o & 31;
        float acc = sbef[j];
#pragma unroll
        for (int k = 0; k < 64; k++) acc += sh[r][k] * sWef[k * 32 + j];
        sz[r][j] = acc;
        int gr = rowBase + r;
        if (gr < n) z_out[gr * 32 + j] = acc;
    }
    __syncthreads();
    for (int o = tid; o < 1024; o += 256) {
        int r = o >> 6, j = o & 63;
        float acc = sbdf[j];
#pragma unroll
        for (int k = 0; k < 32; k++) acc += sz[r][k] * sWdf[k * 64 + j];
        acc = fmaxf(acc, 0.0f);
        int gr = rowBase + r;
        if (gr < n) hd_out[gr * 64 + j] = acc;
    }
    for (int o = tid; o < 48; o += 256) {
        int r = o / 3, j = o % 3;
        float acc = sbc[j];
#pragma unroll
        for (int k = 0; k < 32; k++) acc += sz[r][k] * sWc[k * 3 + j];
        int gr = rowBase + r;
        if (gr < n) pred_out[gr * 3 + j] = acc;
    }
}

// ---------------------------------------------------------------------------
// Host launch
// ---------------------------------------------------------------------------
extern "C" void kernel_launch(void* const* d_in, const int* in_sizes, int n_in,
                              void* d_out, int out_size) {
    const float* x         = (const float*)d_in[0];
    const int*   edge_idx  = (const int*)d_in[1];
    const float* W_enc_gnn = (const float*)d_in[3];
    const float* b_enc_gnn = (const float*)d_in[4];
    const float* W_enc_fc  = (const float*)d_in[5];
    const float* b_enc_fc  = (const float*)d_in[6];
    const float* W_dec_fc  = (const float*)d_in[7];
    const float* b_dec_fc  = (const float*)d_in[8];
    const float* W_dec_gnn = (const float*)d_in[9];
    const float* b_dec_gnn = (const float*)d_in[10];
    const float* W_cond    = (const float*)d_in[11];
    const float* b_cond    = (const float*)d_in[12];

    int N = in_sizes[0] / 256;
    int E = in_sizes[2];
    const int* src = edge_idx;
    const int* dst = edge_idx + E;

    float* out_xrecon = (float*)d_out;
    float* out_z      = out_xrecon + (size_t)N * 256;
    float* out_pred   = out_z + (size_t)N * 32;

    float *p_h1pre, *p_h1, *p_hd, *p_a2;
    int *p_cnt;
    cudaGetSymbolAddress((void**)&p_h1pre, g_h1pre);
    cudaGetSymbolAddress((void**)&p_h1,    g_h1);
    cudaGetSymbolAddress((void**)&p_hd,    g_hd);
    cudaGetSymbolAddress((void**)&p_a2,    g_a2);
    cudaGetSymbolAddress((void**)&p_cnt,   g_cnt);

    cudaFuncSetAttribute(k_mma_gemm1, cudaFuncAttributeMaxDynamicSharedMemorySize, G1_SMEM);
    cudaFuncSetAttribute(k_mma_gemm2, cudaFuncAttributeMaxDynamicSharedMemorySize, G2_SMEM);

    int nbE = (E + 255) / 256;

    cudaMemsetAsync(p_cnt, 0, (size_t)N * sizeof(int), 0);
    k_wconv<<<128, 256>>>(W_enc_gnn, W_dec_gnn);
    k_count<<<nbE, 256>>>(dst, E);
    k_scan_all<<<1, 1024>>>(N, E);
    k_fill<<<nbE, 256>>>(src, dst, E);

    k_mma_gemm1<<<(N + 127) / 128, 256, G1_SMEM>>>(x, p_h1pre, N);
    k_agg64<<<(N + 7) / 8, 256>>>(p_h1pre, b_enc_gnn, p_h1, N, 1);

    k_fused_mid<<<(N + 15) / 16, 256>>>(p_h1, W_enc_fc, b_enc_fc,
                                        W_dec_fc, b_dec_fc, W_cond, b_cond,
                                        out_z, p_hd, out_pred, N);

    k_agg64<<<(N + 7) / 8, 256>>>(p_hd, (const float*)nullptr, p_a2, N, 0);
    k_mma_gemm2<<<(N + 63) / 64, 256, G2_SMEM>>>(p_a2, b_dec_gnn, out_xrecon, N);
}

// round 7
// speedup vs baseline: 1.5689x; 1.5689x over previous
#include <cuda_runtime.h>
#include <cuda_bf16.h>
#include <math.h>
#include <stdint.h>

#define NMAX 50048
#define EMAX 800000

// Scratch (device globals: no allocation allowed)
__device__ float g_h1pre[NMAX * 64];
__device__ float g_h1[NMAX * 64];
__device__ float g_hd[NMAX * 64];
__device__ float g_a2[NMAX * 64];
__device__ float g_dinv[NMAX];
__device__ int   g_cnt[NMAX];
__device__ int   g_cur[NMAX];
__device__ int   g_off[NMAX + 1];
__device__ int2  g_edge[EMAX];     // (src, bits(dinv[s]*dinv[d])) sorted by dst
__device__ int   g_bsums[128];
// bf16 split weights: W1T = W_enc_gnn^T [64 n][256 k], W2T = W_dec_gnn^T [256 n][64 k]
__device__ __nv_bfloat16 g_w1t_hi[64 * 256];
__device__ __nv_bfloat16 g_w1t_lo[64 * 256];
__device__ __nv_bfloat16 g_w2t_hi[256 * 64];
__device__ __nv_bfloat16 g_w2t_lo[256 * 64];

__device__ __forceinline__ uint32_t pack2bf(float a, float b) {
    __nv_bfloat162 t = __floats2bfloat162_rn(a, b);
    return *(uint32_t*)&t;
}
__device__ __forceinline__ float bf_hi_f(float a) {
    return __bfloat162float(__float2bfloat16_rn(a));
}
__device__ __forceinline__ uint32_t prmt7632(uint32_t a, uint32_t b) {
    uint32_t r;
    asm("prmt.b32 %0, %1, %2, 0x7632;" : "=r"(r) : "r"(a), "r"(b));
    return r;
}
// truncation hi/lo split of 8 fp32 -> bf16 hi pack + bf16 lo pack
__device__ __forceinline__ void split8(const float4 f0, const float4 f1,
                                       uint4 &hv, uint4 &lv) {
    uint32_t u0 = __float_as_uint(f0.x), u1 = __float_as_uint(f0.y);
    uint32_t u2 = __float_as_uint(f0.z), u3 = __float_as_uint(f0.w);
    uint32_t u4 = __float_as_uint(f1.x), u5 = __float_as_uint(f1.y);
    uint32_t u6 = __float_as_uint(f1.z), u7 = __float_as_uint(f1.w);
    hv = make_uint4(prmt7632(u0, u1), prmt7632(u2, u3),
                    prmt7632(u4, u5), prmt7632(u6, u7));
    float l0 = f0.x - __uint_as_float(u0 & 0xFFFF0000u);
    float l1 = f0.y - __uint_as_float(u1 & 0xFFFF0000u);
    float l2 = f0.z - __uint_as_float(u2 & 0xFFFF0000u);
    float l3 = f0.w - __uint_as_float(u3 & 0xFFFF0000u);
    float l4 = f1.x - __uint_as_float(u4 & 0xFFFF0000u);
    float l5 = f1.y - __uint_as_float(u5 & 0xFFFF0000u);
    float l6 = f1.z - __uint_as_float(u6 & 0xFFFF0000u);
    float l7 = f1.w - __uint_as_float(u7 & 0xFFFF0000u);
    lv = make_uint4(pack2bf(l0, l1), pack2bf(l2, l3),
                    pack2bf(l4, l5), pack2bf(l6, l7));
}

// mma.sync m16n8k16 bf16 -> f32 accum (portable PTX, lowers to HMMA)
__device__ __forceinline__ void mma16816(float* d, const uint32_t* a, const uint32_t* b) {
    asm volatile(
        "mma.sync.aligned.m16n8k16.row.col.f32.bf16.bf16.f32 "
        "{%0,%1,%2,%3}, {%4,%5,%6,%7}, {%8,%9}, {%0,%1,%2,%3};"
        : "+f"(d[0]), "+f"(d[1]), "+f"(d[2]), "+f"(d[3])
        : "r"(a[0]), "r"(a[1]), "r"(a[2]), "r"(a[3]), "r"(b[0]), "r"(b[1]));
}

// ---------------------------------------------------------------------------
// CSR build (parallel 3-kernel scan, coalesced)
// ---------------------------------------------------------------------------
__global__ void k_count(const int* __restrict__ dst, int E) {
    int e = blockIdx.x * blockDim.x + threadIdx.x;
    if (e < E) atomicAdd(&g_cnt[dst[e]], 1);
}

__global__ void k_scan_bsum(int n) {
    __shared__ int s[1024];
    int i = blockIdx.x * 1024 + threadIdx.x;
    s[threadIdx.x] = (i < n) ? g_cnt[i] : 0;
    __syncthreads();
    for (int st = 512; st > 0; st >>= 1) {
        if (threadIdx.x < st) s[threadIdx.x] += s[threadIdx.x + st];
        __syncthreads();
    }
    if (threadIdx.x == 0) g_bsums[blockIdx.x] = s[0];
}

// tiny: exclusive scan of nb (<=64) block sums, 64 threads
__global__ void k_scan_sums(int nb) {
    __shared__ int s[64];
    int v = (threadIdx.x < nb) ? g_bsums[threadIdx.x] : 0;
    s[threadIdx.x] = v;
    __syncthreads();
    for (int st = 1; st < 64; st <<= 1) {
        int t = (threadIdx.x >= st) ? s[threadIdx.x - st] : 0;
        __syncthreads();
        s[threadIdx.x] += t;
        __syncthreads();
    }
    if (threadIdx.x < nb) g_bsums[threadIdx.x] = s[threadIdx.x] - v;
}

// exclusive offsets + dinv + cursor reset (fused, coalesced, parallel)
__global__ void k_scan_final(int n, int E) {
    __shared__ int s[1024];
    int i = blockIdx.x * 1024 + threadIdx.x;
    int v = (i < n) ? g_cnt[i] : 0;
    s[threadIdx.x] = v;
    __syncthreads();
    for (int st = 1; st < 1024; st <<= 1) {
        int t = (threadIdx.x >= st) ? s[threadIdx.x - st] : 0;
        __syncthreads();
        s[threadIdx.x] += t;
        __syncthreads();
    }
    if (i < n) {
        g_off[i]  = g_bsums[blockIdx.x] + s[threadIdx.x] - v;
        g_dinv[i] = rsqrtf(1.0f + (float)v);
        g_cur[i]  = 0;
    }
    if (i == 0) g_off[n] = E;
}

__global__ void k_fill(const int* __restrict__ src, const int* __restrict__ dst, int E) {
    int e = blockIdx.x * blockDim.x + threadIdx.x;
    if (e < E) {
        int d = dst[e], si = src[e];
        int pos = g_off[d] + atomicAdd(&g_cur[d], 1);
        float w = g_dinv[si] * g_dinv[d];
        g_edge[pos] = make_int2(si, __float_as_int(w));
    }
}

// ---------------------------------------------------------------------------
// Weight transpose + bf16 hi/lo split
// ---------------------------------------------------------------------------
__global__ void k_wconv(const float* __restrict__ W1, const float* __restrict__ W2) {
    int i = blockIdx.x * blockDim.x + threadIdx.x;
    if (i < 64 * 256) {            // W1T[n][k] = W1[k][n]
        int n = i >> 8, k = i & 255;
        float v = W1[k * 64 + n];
        float h = bf_hi_f(v);
        g_w1t_hi[i] = __float2bfloat16_rn(h);
        g_w1t_lo[i] = __float2bfloat16_rn(v - h);
    } else if (i < 2 * 64 * 256) { // W2T[n][k] = W2[k][n]
        int t = i - 64 * 256;
        int n = t >> 6, k = t & 63;
        float v = W2[k * 256 + n];
        float h = bf_hi_f(v);
        g_w2t_hi[t] = __float2bfloat16_rn(h);
        g_w2t_lo[t] = __float2bfloat16_rn(v - h);
    }
}

// ---------------------------------------------------------------------------
// GEMM1 (mma.sync): [M,256]fp32 @ W1 -> [M,64]fp32, block = 128 rows x 64 cols
// ---------------------------------------------------------------------------
#define G1_LDA 72
#define G1_AH  0
#define G1_AL  (128 * 72)
#define G1_BH  (2 * 128 * 72)
#define G1_BL  (2 * 128 * 72 + 64 * 72)
#define G1_SMEM ((2 * 128 * 72 + 2 * 64 * 72) * 2)

__global__ void __launch_bounds__(256) k_mma_gemm1(
    const float* __restrict__ A, float* __restrict__ C, int M) {
    extern __shared__ __align__(16) uint16_t sm1[];
    const int tid = threadIdx.x;
    const int wid = tid >> 5, lane = tid & 31;
    const int g = lane >> 2, tig = lane & 3;
    const int rowBase = blockIdx.x * 128;
    const int warpRow = wid * 16;

    float acc[8][4];
#pragma unroll
    for (int i = 0; i < 8; i++)
#pragma unroll
        for (int j = 0; j < 4; j++) acc[i][j] = 0.0f;

    for (int kc0 = 0; kc0 < 256; kc0 += 64) {
#pragma unroll
        for (int i = 0; i < 4; i++) {
            int c = tid + i * 256;
            int r = c >> 3, k8 = (c & 7) * 8;
            int gr = rowBase + r;
            float4 f0, f1;
            if (gr < M) {
                f0 = *(const float4*)&A[(size_t)gr * 256 + kc0 + k8];
                f1 = *(const float4*)&A[(size_t)gr * 256 + kc0 + k8 + 4];
            } else { f0 = make_float4(0, 0, 0, 0); f1 = f0; }
            uint4 hv, lv;
            split8(f0, f1, hv, lv);
            *(uint4*)&sm1[G1_AH + r * G1_LDA + k8] = hv;
            *(uint4*)&sm1[G1_AL + r * G1_LDA + k8] = lv;
        }
#pragma unroll
        for (int i = 0; i < 2; i++) {
            int c = tid + i * 256;
            int n = c >> 3, k8 = (c & 7) * 8;
            *(uint4*)&sm1[G1_BH + n * G1_LDA + k8] = *(const uint4*)&g_w1t_hi[n * 256 + kc0 + k8];
            *(uint4*)&sm1[G1_BL + n * G1_LDA + k8] = *(const uint4*)&g_w1t_lo[n * 256 + kc0 + k8];
        }
        __syncthreads();
#pragma unroll
        for (int ks = 0; ks < 4; ks++) {
            int col0 = ks * 16 + 2 * tig;
            int col1 = col0 + 8;
            int row0 = warpRow + g, row1 = row0 + 8;
            uint32_t ah[4], al[4];
            ah[0] = *(uint32_t*)&sm1[G1_AH + row0 * G1_LDA + col0];
            ah[1] = *(uint32_t*)&sm1[G1_AH + row1 * G1_LDA + col0];
            ah[2] = *(uint32_t*)&sm1[G1_AH + row0 * G1_LDA + col1];
            ah[3] = *(uint32_t*)&sm1[G1_AH + row1 * G1_LDA + col1];
            al[0] = *(uint32_t*)&sm1[G1_AL + row0 * G1_LDA + col0];
            al[1] = *(uint32_t*)&sm1[G1_AL + row1 * G1_LDA + col0];
            al[2] = *(uint32_t*)&sm1[G1_AL + row0 * G1_LDA + col1];
            al[3] = *(uint32_t*)&sm1[G1_AL + row1 * G1_LDA + col1];
#pragma unroll
            for (int nt = 0; nt < 8; nt++) {
                int nr = nt * 8 + g;
                uint32_t bh[2], bl[2];
                bh[0] = *(uint32_t*)&sm1[G1_BH + nr * G1_LDA + col0];
                bh[1] = *(uint32_t*)&sm1[G1_BH + nr * G1_LDA + col1];
                bl[0] = *(uint32_t*)&sm1[G1_BL + nr * G1_LDA + col0];
                bl[1] = *(uint32_t*)&sm1[G1_BL + nr * G1_LDA + col1];
                mma16816(acc[nt], ah, bh);
                mma16816(acc[nt], ah, bl);
                mma16816(acc[nt], al, bh);
            }
        }
        __syncthreads();
    }
    int gr0 = rowBase + warpRow + g;
    int gr1 = gr0 + 8;
#pragma unroll
    for (int nt = 0; nt < 8; nt++) {
        int col = nt * 8 + 2 * tig;
        if (gr0 < M) *(float2*)&C[(size_t)gr0 * 64 + col] = make_float2(acc[nt][0], acc[nt][1]);
        if (gr1 < M) *(float2*)&C[(size_t)gr1 * 64 + col] = make_float2(acc[nt][2], acc[nt][3]);
    }
}

// ---------------------------------------------------------------------------
// GEMM2 (mma.sync): [M,64]fp32 @ W2 + bias -> [M,256]fp32
// block = 64 rows x 256 cols; warp = 16 rows x 128 cols
// ---------------------------------------------------------------------------
#define G2_LDA 72
#define G2_AH  0
#define G2_AL  (64 * 72)
#define G2_BH  (2 * 64 * 72)
#define G2_BL  (2 * 64 * 72 + 256 * 72)
#define G2_SMEM ((2 * 64 * 72 + 2 * 256 * 72) * 2)

__global__ void __launch_bounds__(256) k_mma_gemm2(
    const float* __restrict__ A, const float* __restrict__ bias,
    float* __restrict__ C, int M) {
    extern __shared__ __align__(16) uint16_t sm2[];
    const int tid = threadIdx.x;
    const int wid = tid >> 5, lane = tid & 31;
    const int g = lane >> 2, tig = lane & 3;
    const int rowBase = blockIdx.x * 64;
    const int warpRow = (wid & 3) * 16;
    const int warpCol = (wid >> 2) * 128;

#pragma unroll
    for (int i = 0; i < 2; i++) {
        int c = tid + i * 256;
        int r = c >> 3, k8 = (c & 7) * 8;
        int gr = rowBase + r;
        float4 f0, f1;
        if (gr < M) {
            f0 = *(const float4*)&A[(size_t)gr * 64 + k8];
            f1 = *(const float4*)&A[(size_t)gr * 64 + k8 + 4];
        } else { f0 = make_float4(0, 0, 0, 0); f1 = f0; }
        uint4 hv, lv;
        split8(f0, f1, hv, lv);
        *(uint4*)&sm2[G2_AH + r * G2_LDA + k8] = hv;
        *(uint4*)&sm2[G2_AL + r * G2_LDA + k8] = lv;
    }
#pragma unroll
    for (int i = 0; i < 8; i++) {
        int c = tid + i * 256;
        int n = c >> 3, k8 = (c & 7) * 8;
        *(uint4*)&sm2[G2_BH + n * G2_LDA + k8] = *(const uint4*)&g_w2t_hi[n * 64 + k8];
        *(uint4*)&sm2[G2_BL + n * G2_LDA + k8] = *(const uint4*)&g_w2t_lo[n * 64 + k8];
    }
    __syncthreads();

    float acc[16][4];
#pragma unroll
    for (int i = 0; i < 16; i++)
#pragma unroll
        for (int j = 0; j < 4; j++) acc[i][j] = 0.0f;

#pragma unroll
    for (int ks = 0; ks < 4; ks++) {
        int col0 = ks * 16 + 2 * tig;
        int col1 = col0 + 8;
        int row0 = warpRow + g, row1 = row0 + 8;
        uint32_t ah[4], al[4];
        ah[0] = *(uint32_t*)&sm2[G2_AH + row0 * G2_LDA + col0];
        ah[1] = *(uint32_t*)&sm2[G2_AH + row1 * G2_LDA + col0];
        ah[2] = *(uint32_t*)&sm2[G2_AH + row0 * G2_LDA + col1];
        ah[3] = *(uint32_t*)&sm2[G2_AH + row1 * G2_LDA + col1];
        al[0] = *(uint32_t*)&sm2[G2_AL + row0 * G2_LDA + col0];
        al[1] = *(uint32_t*)&sm2[G2_AL + row1 * G2_LDA + col0];
        al[2] = *(uint32_t*)&sm2[G2_AL + row0 * G2_LDA + col1];
        al[3] = *(uint32_t*)&sm2[G2_AL + row1 * G2_LDA + col1];
#pragma unroll
        for (int nt = 0; nt < 16; nt++) {
            int nr = warpCol + nt * 8 + g;
            uint32_t bh[2], bl[2];
            bh[0] = *(uint32_t*)&sm2[G2_BH + nr * G2_LDA + col0];
            bh[1] = *(uint32_t*)&sm2[G2_BH + nr * G2_LDA + col1];
            bl[0] = *(uint32_t*)&sm2[G2_BL + nr * G2_LDA + col0];
            bl[1] = *(uint32_t*)&sm2[G2_BL + nr * G2_LDA + col1];
            mma16816(acc[nt], ah, bh);
            mma16816(acc[nt], ah, bl);
            mma16816(acc[nt], al, bh);
        }
    }
    int gr0 = rowBase + warpRow + g;
    int gr1 = gr0 + 8;
#pragma unroll
    for (int nt = 0; nt < 16; nt++) {
        int col = warpCol + nt * 8 + 2 * tig;
        float2 bv = *(const float2*)&bias[col];
        if (gr0 < M)
            *(float2*)&C[(size_t)gr0 * 256 + col] = make_float2(acc[nt][0] + bv.x, acc[nt][1] + bv.y);
        if (gr1 < M)
            *(float2*)&C[(size_t)gr1 * 256 + col] = make_float2(acc[nt][2] + bv.x, acc[nt][3] + bv.y);
    }
}

// ---------------------------------------------------------------------------
// CSR aggregation (warp per node, float2 per lane, precomputed edge weights)
// ---------------------------------------------------------------------------
__global__ void k_agg64(const float* __restrict__ h,
                        const float* __restrict__ bias,
                        float* __restrict__ out, int n, int relu) {
    int node = blockIdx.x * 8 + (threadIdx.x >> 5);
    if (node >= n) return;
    int lane = threadIdx.x & 31;
    const float2* __restrict__ h2 = (const float2*)h;
    float dn = g_dinv[node];
    float2 self = h2[node * 32 + lane];
    float ax = self.x * dn * dn;
    float ay = self.y * dn * dn;
    int p = g_off[node], end = g_off[node + 1];
    for (; p + 3 < end; p += 4) {
        int2 e0 = g_edge[p],     e1 = g_edge[p + 1];
        int2 e2 = g_edge[p + 2], e3 = g_edge[p + 3];
        float2 v0 = h2[e0.x * 32 + lane];
        float2 v1 = h2[e1.x * 32 + lane];
        float2 v2 = h2[e2.x * 32 + lane];
        float2 v3 = h2[e3.x * 32 + lane];
        float w0 = __int_as_float(e0.y), w1 = __int_as_float(e1.y);
        float w2 = __int_as_float(e2.y), w3 = __int_as_float(e3.y);
        ax += v0.x * w0 + v1.x * w1 + v2.x * w2 + v3.x * w3;
        ay += v0.y * w0 + v1.y * w1 + v2.y * w2 + v3.y * w3;
    }
    for (; p < end; p++) {
        int2 e = g_edge[p];
        float w = __int_as_float(e.y);
        float2 v = h2[e.x * 32 + lane];
        ax += v.x * w;
        ay += v.y * w;
    }
    if (bias) {
        float2 b = ((const float2*)bias)[lane];
        ax += b.x; ay += b.y;
    }
    if (relu) { ax = fmaxf(ax, 0.0f); ay = fmaxf(ay, 0.0f); }
    ((float2*)out)[node * 32 + lane] = make_float2(ax, ay);
}

// ---------------------------------------------------------------------------
// Fused mid: z, hd, pred
// ---------------------------------------------------------------------------
__global__ void k_fused_mid(const float* __restrict__ h1,
                            const float* __restrict__ Wef, const float* __restrict__ bef,
                            const float* __restrict__ Wdf, const float* __restrict__ bdf,
                            const float* __restrict__ Wc,  const float* __restrict__ bc,
                            float* __restrict__ z_out, float* __restrict__ hd_out,
                            float* __restrict__ pred_out, int n) {
    __shared__ float sWef[64 * 32];
    __shared__ float sWdf[32 * 64];
    __shared__ float sWc[32 * 3];
    __shared__ float sbef[32], sbdf[64], sbc[3];
    __shared__ float sh[16][64];
    __shared__ float sz[16][32];
    int tid = threadIdx.x;  // 256
    for (int i = tid; i < 64 * 32; i += 256) sWef[i] = Wef[i];
    for (int i = tid; i < 32 * 64; i += 256) sWdf[i] = Wdf[i];
    for (int i = tid; i < 32 * 3; i += 256) sWc[i] = Wc[i];
    if (tid < 32) sbef[tid] = bef[tid];
    if (tid < 64) sbdf[tid] = bdf[tid];
    if (tid < 3)  sbc[tid]  = bc[tid];
    int rowBase = blockIdx.x * 16;
    for (int i = tid; i < 16 * 64; i += 256) {
        int r = i >> 6, c = i & 63;
        int gr = rowBase + r;
        sh[r][c] = (gr < n) ? h1[gr * 64 + c] : 0.0f;
    }
    __syncthreads();
    for (int o = tid; o < 512; o += 256) {
        int r = o >> 5, j = o & 31;
        float acc = sbef[j];
#pragma unroll
        for (int k = 0; k < 64; k++) acc += sh[r][k] * sWef[k * 32 + j];
        sz[r][j] = acc;
        int gr = rowBase + r;
        if (gr < n) z_out[gr * 32 + j] = acc;
    }
    __syncthreads();
    for (int o = tid; o < 1024; o += 256) {
        int r = o >> 6, j = o & 63;
        float acc = sbdf[j];
#pragma unroll
        for (int k = 0; k < 32; k++) acc += sz[r][k] * sWdf[k * 64 + j];
        acc = fmaxf(acc, 0.0f);
        int gr = rowBase + r;
        if (gr < n) hd_out[gr * 64 + j] = acc;
    }
    for (int o = tid; o < 48; o += 256) {
        int r = o / 3, j = o % 3;
        float acc = sbc[j];
#pragma unroll
        for (int k = 0; k < 32; k++) acc += sz[r][k] * sWc[k * 3 + j];
        int gr = rowBase + r;
        if (gr < n) pred_out[gr * 3 + j] = acc;
    }
}

// ---------------------------------------------------------------------------
// Host launch
// ---------------------------------------------------------------------------
extern "C" void kernel_launch(void* const* d_in, const int* in_sizes, int n_in,
                              void* d_out, int out_size) {
    const float* x         = (const float*)d_in[0];
    const int*   edge_idx  = (const int*)d_in[1];
    const float* W_enc_gnn = (const float*)d_in[3];
    const float* b_enc_gnn = (const float*)d_in[4];
    const float* W_enc_fc  = (const float*)d_in[5];
    const float* b_enc_fc  = (const float*)d_in[6];
    const float* W_dec_fc  = (const float*)d_in[7];
    const float* b_dec_fc  = (const float*)d_in[8];
    const float* W_dec_gnn = (const float*)d_in[9];
    const float* b_dec_gnn = (const float*)d_in[10];
    const float* W_cond    = (const float*)d_in[11];
    const float* b_cond    = (const float*)d_in[12];

    int N = in_sizes[0] / 256;
    int E = in_sizes[2];
    const int* src = edge_idx;
    const int* dst = edge_idx + E;

    float* out_xrecon = (float*)d_out;
    float* out_z      = out_xrecon + (size_t)N * 256;
    float* out_pred   = out_z + (size_t)N * 32;

    float *p_h1pre, *p_h1, *p_hd, *p_a2;
    int *p_cnt;
    cudaGetSymbolAddress((void**)&p_h1pre, g_h1pre);
    cudaGetSymbolAddress((void**)&p_h1,    g_h1);
    cudaGetSymbolAddress((void**)&p_hd,    g_hd);
    cudaGetSymbolAddress((void**)&p_a2,    g_a2);
    cudaGetSymbolAddress((void**)&p_cnt,   g_cnt);

    cudaFuncSetAttribute(k_mma_gemm1, cudaFuncAttributeMaxDynamicSharedMemorySize, G1_SMEM);
    cudaFuncSetAttribute(k_mma_gemm2, cudaFuncAttributeMaxDynamicSharedMemorySize, G2_SMEM);

    int nbE  = (E + 255) / 256;
    int nbSc = (N + 1023) / 1024;

    cudaMemsetAsync(p_cnt, 0, (size_t)N * sizeof(int), 0);
    k_wconv<<<128, 256>>>(W_enc_gnn, W_dec_gnn);
    k_count<<<nbE, 256>>>(dst, E);
    k_scan_bsum<<<nbSc, 1024>>>(N);
    k_scan_sums<<<1, 64>>>(nbSc);
    k_scan_final<<<nbSc, 1024>>>(N, E);
    k_fill<<<nbE, 256>>>(src, dst, E);

    k_mma_gemm1<<<(N + 127) / 128, 256, G1_SMEM>>>(x, p_h1pre, N);
    k_agg64<<<(N + 7) / 8, 256>>>(p_h1pre, b_enc_gnn, p_h1, N, 1);

    k_fused_mid<<<(N + 15) / 16, 256>>>(p_h1, W_enc_fc, b_enc_fc,
                                        W_dec_fc, b_dec_fc, W_cond, b_cond,
                                        out_z, p_hd, out_pred, N);

    k_agg64<<<(N + 7) / 8, 256>>>(p_hd, (const float*)nullptr, p_a2, N, 0);
    k_mma_gemm2<<<(N + 63) / 64, 256, G2_SMEM>>>(p_a2, b_dec_gnn, out_xrecon, N);
}

// round 10
// speedup vs baseline: 1.6130x; 1.0281x over previous
#include <cuda_runtime.h>
#include <cuda_bf16.h>
#include <math.h>
#include <stdint.h>

#define NMAX 50048
#define EMAX 800000

// Scratch (device globals: no allocation allowed)
__device__ float g_h1pre[NMAX * 64];
__device__ float g_h1[NMAX * 64];
__device__ float g_hd[NMAX * 64];
__device__ float g_a2[NMAX * 64];
__device__ float g_dinv[NMAX];
__device__ int   g_cnt[NMAX];
__device__ int   g_cur[NMAX];
__device__ int   g_off[NMAX + 1];
__device__ int2  g_edge[EMAX];     // (src, bits(dinv[s]*dinv[d])) sorted by dst
__device__ int   g_bsums[128];
// bf16 split weights: W1T = W_enc_gnn^T [64 n][256 k], W2T = W_dec_gnn^T [256 n][64 k]
__device__ __nv_bfloat16 g_w1t_hi[64 * 256];
__device__ __nv_bfloat16 g_w1t_lo[64 * 256];
__device__ __nv_bfloat16 g_w2t_hi[256 * 64];
__device__ __nv_bfloat16 g_w2t_lo[256 * 64];

__device__ __forceinline__ uint32_t pack2bf(float a, float b) {
    __nv_bfloat162 t = __floats2bfloat162_rn(a, b);
    return *(uint32_t*)&t;
}
__device__ __forceinline__ float bf_hi_f(float a) {
    return __bfloat162float(__float2bfloat16_rn(a));
}
__device__ __forceinline__ uint32_t prmt7632(uint32_t a, uint32_t b) {
    uint32_t r;
    asm("prmt.b32 %0, %1, %2, 0x7632;" : "=r"(r) : "r"(a), "r"(b));
    return r;
}
// truncation hi/lo split of 8 fp32 -> bf16 hi pack + bf16 lo pack
__device__ __forceinline__ void split8(const float4 f0, const float4 f1,
                                       uint4 &hv, uint4 &lv) {
    uint32_t u0 = __float_as_uint(f0.x), u1 = __float_as_uint(f0.y);
    uint32_t u2 = __float_as_uint(f0.z), u3 = __float_as_uint(f0.w);
    uint32_t u4 = __float_as_uint(f1.x), u5 = __float_as_uint(f1.y);
    uint32_t u6 = __float_as_uint(f1.z), u7 = __float_as_uint(f1.w);
    hv = make_uint4(prmt7632(u0, u1), prmt7632(u2, u3),
                    prmt7632(u4, u5), prmt7632(u6, u7));
    float l0 = f0.x - __uint_as_float(u0 & 0xFFFF0000u);
    float l1 = f0.y - __uint_as_float(u1 & 0xFFFF0000u);
    float l2 = f0.z - __uint_as_float(u2 & 0xFFFF0000u);
    float l3 = f0.w - __uint_as_float(u3 & 0xFFFF0000u);
    float l4 = f1.x - __uint_as_float(u4 & 0xFFFF0000u);
    float l5 = f1.y - __uint_as_float(u5 & 0xFFFF0000u);
    float l6 = f1.z - __uint_as_float(u6 & 0xFFFF0000u);
    float l7 = f1.w - __uint_as_float(u7 & 0xFFFF0000u);
    lv = make_uint4(pack2bf(l0, l1), pack2bf(l2, l3),
                    pack2bf(l4, l5), pack2bf(l6, l7));
}

// mma.sync m16n8k16 bf16 -> f32 accum (portable PTX, lowers to HMMA)
__device__ __forceinline__ void mma16816(float* d, const uint32_t* a, const uint32_t* b) {
    asm volatile(
        "mma.sync.aligned.m16n8k16.row.col.f32.bf16.bf16.f32 "
        "{%0,%1,%2,%3}, {%4,%5,%6,%7}, {%8,%9}, {%0,%1,%2,%3};"
        : "+f"(d[0]), "+f"(d[1]), "+f"(d[2]), "+f"(d[3])
        : "r"(a[0]), "r"(a[1]), "r"(a[2]), "r"(a[3]), "r"(b[0]), "r"(b[1]));
}

// ---------------------------------------------------------------------------
// CSR build (parallel 3-kernel scan, coalesced)
// ---------------------------------------------------------------------------
__global__ void k_count(const int* __restrict__ dst, int E) {
    int e = blockIdx.x * blockDim.x + threadIdx.x;
    if (e < E) atomicAdd(&g_cnt[dst[e]], 1);
}

__global__ void k_scan_bsum(int n) {
    __shared__ int s[1024];
    int i = blockIdx.x * 1024 + threadIdx.x;
    s[threadIdx.x] = (i < n) ? g_cnt[i] : 0;
    __syncthreads();
    for (int st = 512; st > 0; st >>= 1) {
        if (threadIdx.x < st) s[threadIdx.x] += s[threadIdx.x + st];
        __syncthreads();
    }
    if (threadIdx.x == 0) g_bsums[blockIdx.x] = s[0];
}

// tiny: exclusive scan of nb (<=64) block sums, 64 threads
__global__ void k_scan_sums(int nb) {
    __shared__ int s[64];
    int v = (threadIdx.x < nb) ? g_bsums[threadIdx.x] : 0;
    s[threadIdx.x] = v;
    __syncthreads();
    for (int st = 1; st < 64; st <<= 1) {
        int t = (threadIdx.x >= st) ? s[threadIdx.x - st] : 0;
        __syncthreads();
        s[threadIdx.x] += t;
        __syncthreads();
    }
    if (threadIdx.x < nb) g_bsums[threadIdx.x] = s[threadIdx.x] - v;
}

// exclusive offsets + dinv + cursor reset (fused, coalesced, parallel)
__global__ void k_scan_final(int n, int E) {
    __shared__ int s[1024];
    int i = blockIdx.x * 1024 + threadIdx.x;
    int v = (i < n) ? g_cnt[i] : 0;
    s[threadIdx.x] = v;
    __syncthreads();
    for (int st = 1; st < 1024; st <<= 1) {
        int t = (threadIdx.x >= st) ? s[threadIdx.x - st] : 0;
        __syncthreads();
        s[threadIdx.x] += t;
        __syncthreads();
    }
    if (i < n) {
        g_off[i]  = g_bsums[blockIdx.x] + s[threadIdx.x] - v;
        g_dinv[i] = rsqrtf(1.0f + (float)v);
        g_cur[i]  = 0;
    }
    if (i == 0) g_off[n] = E;
}

__global__ void k_fill(const int* __restrict__ src, const int* __restrict__ dst, int E) {
    int e = blockIdx.x * blockDim.x + threadIdx.x;
    if (e < E) {
        int d = dst[e], si = src[e];
        int pos = g_off[d] + atomicAdd(&g_cur[d], 1);
        float w = g_dinv[si] * g_dinv[d];
        g_edge[pos] = make_int2(si, __float_as_int(w));
    }
}

// ---------------------------------------------------------------------------
// Weight transpose + bf16 hi/lo split
// ---------------------------------------------------------------------------
__global__ void k_wconv(const float* __restrict__ W1, const float* __restrict__ W2) {
    int i = blockIdx.x * blockDim.x + threadIdx.x;
    if (i < 64 * 256) {            // W1T[n][k] = W1[k][n]
        int n = i >> 8, k = i & 255;
        float v = W1[k * 64 + n];
        float h = bf_hi_f(v);
        g_w1t_hi[i] = __float2bfloat16_rn(h);
        g_w1t_lo[i] = __float2bfloat16_rn(v - h);
    } else if (i < 2 * 64 * 256) { // W2T[n][k] = W2[k][n]
        int t = i - 64 * 256;
        int n = t >> 6, k = t & 63;
        float v = W2[k * 256 + n];
        float h = bf_hi_f(v);
        g_w2t_hi[t] = __float2bfloat16_rn(h);
        g_w2t_lo[t] = __float2bfloat16_rn(v - h);
    }
}

// ---------------------------------------------------------------------------
// GEMM1 (mma.sync): [M,256]fp32 @ W1 -> [M,64]fp32, block = 128 rows x 64 cols
// ---------------------------------------------------------------------------
#define G1_LDA 72
#define G1_AH  0
#define G1_AL  (128 * 72)
#define G1_BH  (2 * 128 * 72)
#define G1_BL  (2 * 128 * 72 + 64 * 72)
#define G1_SMEM ((2 * 128 * 72 + 2 * 64 * 72) * 2)

__global__ void __launch_bounds__(256) k_mma_gemm1(
    const float* __restrict__ A, float* __restrict__ C, int M) {
    extern __shared__ __align__(16) uint16_t sm1[];
    const int tid = threadIdx.x;
    const int wid = tid >> 5, lane = tid & 31;
    const int g = lane >> 2, tig = lane & 3;
    const int rowBase = blockIdx.x * 128;
    const int warpRow = wid * 16;

    float acc[8][4];
#pragma unroll
    for (int i = 0; i < 8; i++)
#pragma unroll
        for (int j = 0; j < 4; j++) acc[i][j] = 0.0f;

    for (int kc0 = 0; kc0 < 256; kc0 += 64) {
#pragma unroll
        for (int i = 0; i < 4; i++) {
            int c = tid + i * 256;
            int r = c >> 3, k8 = (c & 7) * 8;
            int gr = rowBase + r;
            float4 f0, f1;
            if (gr < M) {
                f0 = *(const float4*)&A[(size_t)gr * 256 + kc0 + k8];
                f1 = *(const float4*)&A[(size_t)gr * 256 + kc0 + k8 + 4];
            } else { f0 = make_float4(0, 0, 0, 0); f1 = f0; }
            uint4 hv, lv;
            split8(f0, f1, hv, lv);
            *(uint4*)&sm1[G1_AH + r * G1_LDA + k8] = hv;
            *(uint4*)&sm1[G1_AL + r * G1_LDA + k8] = lv;
        }
#pragma unroll
        for (int i = 0; i < 2; i++) {
            int c = tid + i * 256;
            int n = c >> 3, k8 = (c & 7) * 8;
            *(uint4*)&sm1[G1_BH + n * G1_LDA + k8] = *(const uint4*)&g_w1t_hi[n * 256 + kc0 + k8];
            *(uint4*)&sm1[G1_BL + n * G1_LDA + k8] = *(const uint4*)&g_w1t_lo[n * 256 + kc0 + k8];
        }
        __syncthreads();
#pragma unroll
        for (int ks = 0; ks < 4; ks++) {
            int col0 = ks * 16 + 2 * tig;
            int col1 = col0 + 8;
            int row0 = warpRow + g, row1 = row0 + 8;
            uint32_t ah[4], al[4];
            ah[0] = *(uint32_t*)&sm1[G1_AH + row0 * G1_LDA + col0];
            ah[1] = *(uint32_t*)&sm1[G1_AH + row1 * G1_LDA + col0];
            ah[2] = *(uint32_t*)&sm1[G1_AH + row0 * G1_LDA + col1];
            ah[3] = *(uint32_t*)&sm1[G1_AH + row1 * G1_LDA + col1];
            al[0] = *(uint32_t*)&sm1[G1_AL + row0 * G1_LDA + col0];
            al[1] = *(uint32_t*)&sm1[G1_AL + row1 * G1_LDA + col0];
            al[2] = *(uint32_t*)&sm1[G1_AL + row0 * G1_LDA + col1];
            al[3] = *(uint32_t*)&sm1[G1_AL + row1 * G1_LDA + col1];
#pragma unroll
            for (int nt = 0; nt < 8; nt++) {
                int nr = nt * 8 + g;
                uint32_t bh[2], bl[2];
                bh[0] = *(uint32_t*)&sm1[G1_BH + nr * G1_LDA + col0];
                bh[1] = *(uint32_t*)&sm1[G1_BH + nr * G1_LDA + col1];
                bl[0] = *(uint32_t*)&sm1[G1_BL + nr * G1_LDA + col0];
                bl[1] = *(uint32_t*)&sm1[G1_BL + nr * G1_LDA + col1];
                mma16816(acc[nt], ah, bh);
                mma16816(acc[nt], ah, bl);
                mma16816(acc[nt], al, bh);
            }
        }
        __syncthreads();
    }
    int gr0 = rowBase + warpRow + g;
    int gr1 = gr0 + 8;
#pragma unroll
    for (int nt = 0; nt < 8; nt++) {
        int col = nt * 8 + 2 * tig;
        if (gr0 < M) *(float2*)&C[(size_t)gr0 * 64 + col] = make_float2(acc[nt][0], acc[nt][1]);
        if (gr1 < M) *(float2*)&C[(size_t)gr1 * 64 + col] = make_float2(acc[nt][2], acc[nt][3]);
    }
}

// ---------------------------------------------------------------------------
// GEMM2 (mma.sync): [M,64]fp32 @ W2 + bias -> [M,256]fp32
// block = 64 rows x 256 cols; warp = 16 rows x 128 cols
// ---------------------------------------------------------------------------
#define G2_LDA 72
#define G2_AH  0
#define G2_AL  (64 * 72)
#define G2_BH  (2 * 64 * 72)
#define G2_BL  (2 * 64 * 72 + 256 * 72)
#define G2_SMEM ((2 * 64 * 72 + 2 * 256 * 72) * 2)

__global__ void __launch_bounds__(256) k_mma_gemm2(
    const float* __restrict__ A, const float* __restrict__ bias,
    float* __restrict__ C, int M) {
    extern __shared__ __align__(16) uint16_t sm2[];
    const int tid = threadIdx.x;
    const int wid = tid >> 5, lane = tid & 31;
    const int g = lane >> 2, tig = lane & 3;
    const int rowBase = blockIdx.x * 64;
    const int warpRow = (wid & 3) * 16;
    const int warpCol = (wid >> 2) * 128;

#pragma unroll
    for (int i = 0; i < 2; i++) {
        int c = tid + i * 256;
        int r = c >> 3, k8 = (c & 7) * 8;
        int gr = rowBase + r;
        float4 f0, f1;
        if (gr < M) {
            f0 = *(const float4*)&A[(size_t)gr * 64 + k8];
            f1 = *(const float4*)&A[(size_t)gr * 64 + k8 + 4];
        } else { f0 = make_float4(0, 0, 0, 0); f1 = f0; }
        uint4 hv, lv;
        split8(f0, f1, hv, lv);
        *(uint4*)&sm2[G2_AH + r * G2_LDA + k8] = hv;
        *(uint4*)&sm2[G2_AL + r * G2_LDA + k8] = lv;
    }
#pragma unroll
    for (int i = 0; i < 8; i++) {
        int c = tid + i * 256;
        int n = c >> 3, k8 = (c & 7) * 8;
        *(uint4*)&sm2[G2_BH + n * G2_LDA + k8] = *(const uint4*)&g_w2t_hi[n * 64 + k8];
        *(uint4*)&sm2[G2_BL + n * G2_LDA + k8] = *(const uint4*)&g_w2t_lo[n * 64 + k8];
    }
    __syncthreads();

    float acc[16][4];
#pragma unroll
    for (int i = 0; i < 16; i++)
#pragma unroll
        for (int j = 0; j < 4; j++) acc[i][j] = 0.0f;

#pragma unroll
    for (int ks = 0; ks < 4; ks++) {
        int col0 = ks * 16 + 2 * tig;
        int col1 = col0 + 8;
        int row0 = warpRow + g, row1 = row0 + 8;
        uint32_t ah[4], al[4];
        ah[0] = *(uint32_t*)&sm2[G2_AH + row0 * G2_LDA + col0];
        ah[1] = *(uint32_t*)&sm2[G2_AH + row1 * G2_LDA + col0];
        ah[2] = *(uint32_t*)&sm2[G2_AH + row0 * G2_LDA + col1];
        ah[3] = *(uint32_t*)&sm2[G2_AH + row1 * G2_LDA + col1];
        al[0] = *(uint32_t*)&sm2[G2_AL + row0 * G2_LDA + col0];
        al[1] = *(uint32_t*)&sm2[G2_AL + row1 * G2_LDA + col0];
        al[2] = *(uint32_t*)&sm2[G2_AL + row0 * G2_LDA + col1];
        al[3] = *(uint32_t*)&sm2[G2_AL + row1 * G2_LDA + col1];
#pragma unroll
        for (int nt = 0; nt < 16; nt++) {
            int nr = warpCol + nt * 8 + g;
            uint32_t bh[2], bl[2];
            bh[0] = *(uint32_t*)&sm2[G2_BH + nr * G2_LDA + col0];
            bh[1] = *(uint32_t*)&sm2[G2_BH + nr * G2_LDA + col1];
            bl[0] = *(uint32_t*)&sm2[G2_BL + nr * G2_LDA + col0];
            bl[1] = *(uint32_t*)&sm2[G2_BL + nr * G2_LDA + col1];
            mma16816(acc[nt], ah, bh);
            mma16816(acc[nt], ah, bl);
            mma16816(acc[nt], al, bh);
        }
    }
    int gr0 = rowBase + warpRow + g;
    int gr1 = gr0 + 8;
#pragma unroll
    for (int nt = 0; nt < 16; nt++) {
        int col = warpCol + nt * 8 + 2 * tig;
        float2 bv = *(const float2*)&bias[col];
        if (gr0 < M)
            *(float2*)&C[(size_t)gr0 * 256 + col] = make_float2(acc[nt][0] + bv.x, acc[nt][1] + bv.y);
        if (gr1 < M)
            *(float2*)&C[(size_t)gr1 * 256 + col] = make_float2(acc[nt][2] + bv.x, acc[nt][3] + bv.y);
    }
}

// ---------------------------------------------------------------------------
// CSR aggregation (warp per node, float2 per lane, precomputed edge weights)
// ---------------------------------------------------------------------------
__global__ void k_agg64(const float* __restrict__ h,
                        const float* __restrict__ bias,
                        float* __restrict__ out, int n, int relu) {
    int node = blockIdx.x * 8 + (threadIdx.x >> 5);
    if (node >= n) return;
    int lane = threadIdx.x & 31;
    const float2* __restrict__ h2 = (const float2*)h;
    float dn = g_dinv[node];
    float2 self = h2[node * 32 + lane];
    float ax = self.x * dn * dn;
    float ay = self.y * dn * dn;
    int p = g_off[node], end = g_off[node + 1];
    for (; p + 3 < end; p += 4) {
        int2 e0 = g_edge[p],     e1 = g_edge[p + 1];
        int2 e2 = g_edge[p + 2], e3 = g_edge[p + 3];
        float2 v0 = h2[e0.x * 32 + lane];
        float2 v1 = h2[e1.x * 32 + lane];
        float2 v2 = h2[e2.x * 32 + lane];
        float2 v3 = h2[e3.x * 32 + lane];
        float w0 = __int_as_float(e0.y), w1 = __int_as_float(e1.y);
        float w2 = __int_as_float(e2.y), w3 = __int_as_float(e3.y);
        ax += v0.x * w0 + v1.x * w1 + v2.x * w2 + v3.x * w3;
        ay += v0.y * w0 + v1.y * w1 + v2.y * w2 + v3.y * w3;
    }
    for (; p < end; p++) {
        int2 e = g_edge[p];
        float w = __int_as_float(e.y);
        float2 v = h2[e.x * 32 + lane];
        ax += v.x * w;
        ay += v.y * w;
    }
    if (bias) {
        float2 b = ((const float2*)bias)[lane];
        ax += b.x; ay += b.y;
    }
    if (relu) { ax = fmaxf(ax, 0.0f); ay = fmaxf(ay, 0.0f); }
    ((float2*)out)[node * 32 + lane] = make_float2(ax, ay);
}

// ---------------------------------------------------------------------------
// Fused mid: z, hd, pred
// ---------------------------------------------------------------------------
__global__ void k_fused_mid(const float* __restrict__ h1,
                            const float* __restrict__ Wef, const float* __restrict__ bef,
                            const float* __restrict__ Wdf, const float* __restrict__ bdf,
                            const float* __restrict__ Wc,  const float* __restrict__ bc,
                            float* __restrict__ z_out, float* __restrict__ hd_out,
                            float* __restrict__ pred_out, int n) {
    __shared__ float sWef[64 * 32];
    __shared__ float sWdf[32 * 64];
    __shared__ float sWc[32 * 3];
    __shared__ float sbef[32], sbdf[64], sbc[3];
    __shared__ float sh[16][64];
    __shared__ float sz[16][32];
    int tid = threadIdx.x;  // 256
    for (int i = tid; i < 64 * 32; i += 256) sWef[i] = Wef[i];
    for (int i = tid; i < 32 * 64; i += 256) sWdf[i] = Wdf[i];
    for (int i = tid; i < 32 * 3; i += 256) sWc[i] = Wc[i];
    if (tid < 32) sbef[tid] = bef[tid];
    if (tid < 64) sbdf[tid] = bdf[tid];
    if (tid < 3)  sbc[tid]  = bc[tid];
    int rowBase = blockIdx.x * 16;
    for (int i = tid; i < 16 * 64; i += 256) {
        int r = i >> 6, c = i & 63;
        int gr = rowBase + r;
        sh[r][c] = (gr < n) ? h1[gr * 64 + c] : 0.0f;
    }
    __syncthreads();
    for (int o = tid; o < 512; o += 256) {
        int r = o >> 5, j = o & 31;
        float acc = sbef[j];
#pragma unroll
        for (int k = 0; k < 64; k++) acc += sh[r][k] * sWef[k * 32 + j];
        sz[r][j] = acc;
        int gr = rowBase + r;
        if (gr < n) z_out[gr * 32 + j] = acc;
    }
    __syncthreads();
    for (int o = tid; o < 1024; o += 256) {
        int r = o >> 6, j = o & 63;
        float acc = sbdf[j];
#pragma unroll
        for (int k = 0; k < 32; k++) acc += sz[r][k] * sWdf[k * 64 + j];
        acc = fmaxf(acc, 0.0f);
        int gr = rowBase + r;
        if (gr < n) hd_out[gr * 64 + j] = acc;
    }
    for (int o = tid; o < 48; o += 256) {
        int r = o / 3, j = o % 3;
        float acc = sbc[j];
#pragma unroll
        for (int k = 0; k < 32; k++) acc += sz[r][k] * sWc[k * 3 + j];
        int gr = rowBase + r;
        if (gr < n) pred_out[gr * 3 + j] = acc;
    }
}

// ---------------------------------------------------------------------------
// Host launch: fork CSR chain onto side stream, overlap with wconv+GEMM1
// ---------------------------------------------------------------------------
extern "C" void kernel_launch(void* const* d_in, const int* in_sizes, int n_in,
                              void* d_out, int out_size) {
    const float* x         = (const float*)d_in[0];
    const int*   edge_idx  = (const int*)d_in[1];
    const float* W_enc_gnn = (const float*)d_in[3];
    const float* b_enc_gnn = (const float*)d_in[4];
    const float* W_enc_fc  = (const float*)d_in[5];
    const float* b_enc_fc  = (const float*)d_in[6];
    const float* W_dec_fc  = (const float*)d_in[7];
    const float* b_dec_fc  = (const float*)d_in[8];
    const float* W_dec_gnn = (const float*)d_in[9];
    const float* b_dec_gnn = (const float*)d_in[10];
    const float* W_cond    = (const float*)d_in[11];
    const float* b_cond    = (const float*)d_in[12];

    int N = in_sizes[0] / 256;
    int E = in_sizes[2];
    const int* src = edge_idx;
    const int* dst = edge_idx + E;

    float* out_xrecon = (float*)d_out;
    float* out_z      = out_xrecon + (size_t)N * 256;
    float* out_pred   = out_z + (size_t)N * 32;

    float *p_h1pre, *p_h1, *p_hd, *p_a2;
    int *p_cnt;
    cudaGetSymbolAddress((void**)&p_h1pre, g_h1pre);
    cudaGetSymbolAddress((void**)&p_h1,    g_h1);
    cudaGetSymbolAddress((void**)&p_hd,    g_hd);
    cudaGetSymbolAddress((void**)&p_a2,    g_a2);
    cudaGetSymbolAddress((void**)&p_cnt,   g_cnt);

    // one-time setup (no device memory allocation involved)
    static cudaStream_t sCsr = nullptr;
    static cudaEvent_t evFork = nullptr, evCsrDone = nullptr;
    if (!sCsr) {
        cudaStreamCreateWithFlags(&sCsr, cudaStreamNonBlocking);
        cudaEventCreateWithFlags(&evFork, cudaEventDisableTiming);
        cudaEventCreateWithFlags(&evCsrDone, cudaEventDisableTiming);
        cudaFuncSetAttribute(k_mma_gemm1, cudaFuncAttributeMaxDynamicSharedMemorySize, G1_SMEM);
        cudaFuncSetAttribute(k_mma_gemm2, cudaFuncAttributeMaxDynamicSharedMemorySize, G2_SMEM);
    }

    int nbE  = (E + 255) / 256;
    int nbSc = (N + 1023) / 1024;

    // ---- fork: CSR chain on side stream ----
    cudaEventRecord(evFork, 0);
    cudaStreamWaitEvent(sCsr, evFork, 0);

    cudaMemsetAsync(p_cnt, 0, (size_t)N * sizeof(int), sCsr);
    k_count<<<nbE, 256, 0, sCsr>>>(dst, E);
    k_scan_bsum<<<nbSc, 1024, 0, sCsr>>>(N);
    k_scan_sums<<<1, 64, 0, sCsr>>>(nbSc);
    k_scan_final<<<nbSc, 1024, 0, sCsr>>>(N, E);
    k_fill<<<nbE, 256, 0, sCsr>>>(src, dst, E);
    cudaEventRecord(evCsrDone, sCsr);

    // ---- main stream: weights + GEMM1 (independent of CSR) ----
    k_wconv<<<128, 256>>>(W_enc_gnn, W_dec_gnn);
    k_mma_gemm1<<<(N + 127) / 128, 256, G1_SMEM>>>(x, p_h1pre, N);

    // ---- join: aggregation needs both h1pre and the CSR ----
    cudaStreamWaitEvent(0, evCsrDone, 0);

    k_agg64<<<(N + 7) / 8, 256>>>(p_h1pre, b_enc_gnn, p_h1, N, 1);

    k_fused_mid<<<(N + 15) / 16, 256>>>(p_h1, W_enc_fc, b_enc_fc,
                                        W_dec_fc, b_dec_fc, W_cond, b_cond,
                                        out_z, p_hd, out_pred, N);

    k_agg64<<<(N + 7) / 8, 256>>>(p_hd, (const float*)nullptr, p_a2, N, 0);
    k_mma_gemm2<<<(N + 63) / 64, 256, G2_SMEM>>>(p_a2, b_dec_gnn, out_xrecon, N);
}

// round 12
// speedup vs baseline: 1.6374x; 1.0152x over previous
#include <cuda_runtime.h>
#include <cuda_bf16.h>
#include <cuda_fp16.h>
#include <math.h>
#include <stdint.h>

#define NMAX 50048
#define EMAX 800000

// Scratch (device globals: no allocation allowed)
__device__ __half2 g_h1pre[NMAX * 32];   // gemm1 out, fp16 (gather-heavy)
__device__ float   g_h1[NMAX * 64];      // agg1 out (linear access)
__device__ __half2 g_hd[NMAX * 32];      // mid out, fp16 (gather-heavy)
__device__ float   g_a2[NMAX * 64];      // agg2 out (linear access)
__device__ float   g_dinv[NMAX];
__device__ int     g_cnt[NMAX];
__device__ int     g_rank[EMAX];         // within-dst rank, from k_count's atomic
__device__ int     g_off[NMAX + 1];
__device__ int2    g_edge[EMAX];         // (src, bits(dinv[s]*dinv[d])) sorted by dst
__device__ int     g_bsums[128];
// bf16 split weights: W1T = W_enc_gnn^T [64 n][256 k], W2T = W_dec_gnn^T [256 n][64 k]
__device__ __nv_bfloat16 g_w1t_hi[64 * 256];
__device__ __nv_bfloat16 g_w1t_lo[64 * 256];
__device__ __nv_bfloat16 g_w2t_hi[256 * 64];
__device__ __nv_bfloat16 g_w2t_lo[256 * 64];

__device__ __forceinline__ uint32_t pack2bf(float a, float b) {
    __nv_bfloat162 t = __floats2bfloat162_rn(a, b);
    return *(uint32_t*)&t;
}
__device__ __forceinline__ float bf_hi_f(float a) {
    return __bfloat162float(__float2bfloat16_rn(a));
}
__device__ __forceinline__ uint32_t prmt7632(uint32_t a, uint32_t b) {
    uint32_t r;
    asm("prmt.b32 %0, %1, %2, 0x7632;" : "=r"(r) : "r"(a), "r"(b));
    return r;
}
// truncation hi/lo split of 8 fp32 -> bf16 hi pack + bf16 lo pack
__device__ __forceinline__ void split8(const float4 f0, const float4 f1,
                                       uint4 &hv, uint4 &lv) {
    uint32_t u0 = __float_as_uint(f0.x), u1 = __float_as_uint(f0.y);
    uint32_t u2 = __float_as_uint(f0.z), u3 = __float_as_uint(f0.w);
    uint32_t u4 = __float_as_uint(f1.x), u5 = __float_as_uint(f1.y);
    uint32_t u6 = __float_as_uint(f1.z), u7 = __float_as_uint(f1.w);
    hv = make_uint4(prmt7632(u0, u1), prmt7632(u2, u3),
                    prmt7632(u4, u5), prmt7632(u6, u7));
    float l0 = f0.x - __uint_as_float(u0 & 0xFFFF0000u);
    float l1 = f0.y - __uint_as_float(u1 & 0xFFFF0000u);
    float l2 = f0.z - __uint_as_float(u2 & 0xFFFF0000u);
    float l3 = f0.w - __uint_as_float(u3 & 0xFFFF0000u);
    float l4 = f1.x - __uint_as_float(u4 & 0xFFFF0000u);
    float l5 = f1.y - __uint_as_float(u5 & 0xFFFF0000u);
    float l6 = f1.z - __uint_as_float(u6 & 0xFFFF0000u);
    float l7 = f1.w - __uint_as_float(u7 & 0xFFFF0000u);
    lv = make_uint4(pack2bf(l0, l1), pack2bf(l2, l3),
                    pack2bf(l4, l5), pack2bf(l6, l7));
}

// mma.sync m16n8k16 bf16 -> f32 accum (portable PTX, lowers to HMMA)
__device__ __forceinline__ void mma16816(float* d, const uint32_t* a, const uint32_t* b) {
    asm volatile(
        "mma.sync.aligned.m16n8k16.row.col.f32.bf16.bf16.f32 "
        "{%0,%1,%2,%3}, {%4,%5,%6,%7}, {%8,%9}, {%0,%1,%2,%3};"
        : "+f"(d[0]), "+f"(d[1]), "+f"(d[2]), "+f"(d[3])
        : "r"(a[0]), "r"(a[1]), "r"(a[2]), "r"(a[3]), "r"(b[0]), "r"(b[1]));
}

// ---------------------------------------------------------------------------
// CSR build: count (stores rank), parallel scan, atomic-free fill
// ---------------------------------------------------------------------------
__global__ void k_count(const int* __restrict__ dst, int E) {
    int e = blockIdx.x * blockDim.x + threadIdx.x;
    if (e < E) g_rank[e] = atomicAdd(&g_cnt[dst[e]], 1);
}

__global__ void k_scan_bsum(int n) {
    __shared__ int s[1024];
    int i = blockIdx.x * 1024 + threadIdx.x;
    s[threadIdx.x] = (i < n) ? g_cnt[i] : 0;
    __syncthreads();
    for (int st = 512; st > 0; st >>= 1) {
        if (threadIdx.x < st) s[threadIdx.x] += s[threadIdx.x + st];
        __syncthreads();
    }
    if (threadIdx.x == 0) g_bsums[blockIdx.x] = s[0];
}

__global__ void k_scan_sums(int nb) {
    __shared__ int s[64];
    int v = (threadIdx.x < nb) ? g_bsums[threadIdx.x] : 0;
    s[threadIdx.x] = v;
    __syncthreads();
    for (int st = 1; st < 64; st <<= 1) {
        int t = (threadIdx.x >= st) ? s[threadIdx.x - st] : 0;
        __syncthreads();
        s[threadIdx.x] += t;
        __syncthreads();
    }
    if (threadIdx.x < nb) g_bsums[threadIdx.x] = s[threadIdx.x] - v;
}

__global__ void k_scan_final(int n, int E) {
    __shared__ int s[1024];
    int i = blockIdx.x * 1024 + threadIdx.x;
    int v = (i < n) ? g_cnt[i] : 0;
    s[threadIdx.x] = v;
    __syncthreads();
    for (int st = 1; st < 1024; st <<= 1) {
        int t = (threadIdx.x >= st) ? s[threadIdx.x - st] : 0;
        __syncthreads();
        s[threadIdx.x] += t;
        __syncthreads();
    }
    if (i < n) {
        g_off[i]  = g_bsums[blockIdx.x] + s[threadIdx.x] - v;
        g_dinv[i] = rsqrtf(1.0f + (float)v);
    }
    if (i == 0) g_off[n] = E;
}

// atomic-free: rank came from k_count
__global__ void k_fill(const int* __restrict__ src, const int* __restrict__ dst, int E) {
    int e = blockIdx.x * blockDim.x + threadIdx.x;
    if (e < E) {
        int d = dst[e], si = src[e];
        int pos = g_off[d] + g_rank[e];
        float w = g_dinv[si] * g_dinv[d];
        g_edge[pos] = make_int2(si, __float_as_int(w));
    }
}

// ---------------------------------------------------------------------------
// Weight transpose + bf16 hi/lo split
// ---------------------------------------------------------------------------
__global__ void k_wconv(const float* __restrict__ W1, const float* __restrict__ W2) {
    int i = blockIdx.x * blockDim.x + threadIdx.x;
    if (i < 64 * 256) {            // W1T[n][k] = W1[k][n]
        int n = i >> 8, k = i & 255;
        float v = W1[k * 64 + n];
        float h = bf_hi_f(v);
        g_w1t_hi[i] = __float2bfloat16_rn(h);
        g_w1t_lo[i] = __float2bfloat16_rn(v - h);
    } else if (i < 2 * 64 * 256) { // W2T[n][k] = W2[k][n]
        int t = i - 64 * 256;
        int n = t >> 6, k = t & 63;
        float v = W2[k * 256 + n];
        float h = bf_hi_f(v);
        g_w2t_hi[t] = __float2bfloat16_rn(h);
        g_w2t_lo[t] = __float2bfloat16_rn(v - h);
    }
}

// ---------------------------------------------------------------------------
// GEMM1 (mma.sync): [M,256]fp32 @ W1 -> [M,64] fp16 (half2 packed)
// ---------------------------------------------------------------------------
#define G1_LDA 72
#define G1_AH  0
#define G1_AL  (128 * 72)
#define G1_BH  (2 * 128 * 72)
#define G1_BL  (2 * 128 * 72 + 64 * 72)
#define G1_SMEM ((2 * 128 * 72 + 2 * 64 * 72) * 2)

__global__ void __launch_bounds__(256) k_mma_gemm1(
    const float* __restrict__ A, __half2* __restrict__ C, int M) {
    extern __shared__ __align__(16) uint16_t sm1[];
    const int tid = threadIdx.x;
    const int wid = tid >> 5, lane = tid & 31;
    const int g = lane >> 2, tig = lane & 3;
    const int rowBase = blockIdx.x * 128;
    const int warpRow = wid * 16;

    float acc[8][4];
#pragma unroll
    for (int i = 0; i < 8; i++)
#pragma unroll
        for (int j = 0; j < 4; j++) acc[i][j] = 0.0f;

    for (int kc0 = 0; kc0 < 256; kc0 += 64) {
#pragma unroll
        for (int i = 0; i < 4; i++) {
            int c = tid + i * 256;
            int r = c >> 3, k8 = (c & 7) * 8;
            int gr = rowBase + r;
            float4 f0, f1;
            if (gr < M) {
                f0 = *(const float4*)&A[(size_t)gr * 256 + kc0 + k8];
                f1 = *(const float4*)&A[(size_t)gr * 256 + kc0 + k8 + 4];
            } else { f0 = make_float4(0, 0, 0, 0); f1 = f0; }
            uint4 hv, lv;
            split8(f0, f1, hv, lv);
            *(uint4*)&sm1[G1_AH + r * G1_LDA + k8] = hv;
            *(uint4*)&sm1[G1_AL + r * G1_LDA + k8] = lv;
        }
#pragma unroll
        for (int i = 0; i < 2; i++) {
            int c = tid + i * 256;
            int n = c >> 3, k8 = (c & 7) * 8;
            *(uint4*)&sm1[G1_BH + n * G1_LDA + k8] = *(const uint4*)&g_w1t_hi[n * 256 + kc0 + k8];
            *(uint4*)&sm1[G1_BL + n * G1_LDA + k8] = *(const uint4*)&g_w1t_lo[n * 256 + kc0 + k8];
        }
        __syncthreads();
#pragma unroll
        for (int ks = 0; ks < 4; ks++) {
            int col0 = ks * 16 + 2 * tig;
            int col1 = col0 + 8;
            int row0 = warpRow + g, row1 = row0 + 8;
            uint32_t ah[4], al[4];
            ah[0] = *(uint32_t*)&sm1[G1_AH + row0 * G1_LDA + col0];
            ah[1] = *(uint32_t*)&sm1[G1_AH + row1 * G1_LDA + col0];
            ah[2] = *(uint32_t*)&sm1[G1_AH + row0 * G1_LDA + col1];
            ah[3] = *(uint32_t*)&sm1[G1_AH + row1 * G1_LDA + col1];
            al[0] = *(uint32_t*)&sm1[G1_AL + row0 * G1_LDA + col0];
            al[1] = *(uint32_t*)&sm1[G1_AL + row1 * G1_LDA + col0];
            al[2] = *(uint32_t*)&sm1[G1_AL + row0 * G1_LDA + col1];
            al[3] = *(uint32_t*)&sm1[G1_AL + row1 * G1_LDA + col1];
#pragma unroll
            for (int nt = 0; nt < 8; nt++) {
                int nr = nt * 8 + g;
                uint32_t bh[2], bl[2];
                bh[0] = *(uint32_t*)&sm1[G1_BH + nr * G1_LDA + col0];
                bh[1] = *(uint32_t*)&sm1[G1_BH + nr * G1_LDA + col1];
                bl[0] = *(uint32_t*)&sm1[G1_BL + nr * G1_LDA + col0];
                bl[1] = *(uint32_t*)&sm1[G1_BL + nr * G1_LDA + col1];
                mma16816(acc[nt], ah, bh);
                mma16816(acc[nt], ah, bl);
                mma16816(acc[nt], al, bh);
            }
        }
        __syncthreads();
    }
    int gr0 = rowBase + warpRow + g;
    int gr1 = gr0 + 8;
#pragma unroll
    for (int nt = 0; nt < 8; nt++) {
        int cp = nt * 4 + tig;   // half2 column index (= col/2)
        if (gr0 < M) C[(size_t)gr0 * 32 + cp] = __floats2half2_rn(acc[nt][0], acc[nt][1]);
        if (gr1 < M) C[(size_t)gr1 * 32 + cp] = __floats2half2_rn(acc[nt][2], acc[nt][3]);
    }
}

// ---------------------------------------------------------------------------
// GEMM2 (mma.sync): [M,64]fp32 @ W2 + bias -> [M,256]fp32
// ---------------------------------------------------------------------------
#define G2_LDA 72
#define G2_AH  0
#define G2_AL  (64 * 72)
#define G2_BH  (2 * 64 * 72)
#define G2_BL  (2 * 64 * 72 + 256 * 72)
#define G2_SMEM ((2 * 64 * 72 + 2 * 256 * 72) * 2)

__global__ void __launch_bounds__(256) k_mma_gemm2(
    const float* __restrict__ A, const float* __restrict__ bias,
    float* __restrict__ C, int M) {
    extern __shared__ __align__(16) uint16_t sm2[];
    const int tid = threadIdx.x;
    const int wid = tid >> 5, lane = tid & 31;
    const int g = lane >> 2, tig = lane & 3;
    const int rowBase = blockIdx.x * 64;
    const int warpRow = (wid & 3) * 16;
    const int warpCol = (wid >> 2) * 128;

#pragma unroll
    for (int i = 0; i < 2; i++) {
        int c = tid + i * 256;
        int r = c >> 3, k8 = (c & 7) * 8;
        int gr = rowBase + r;
        float4 f0, f1;
        if (gr < M) {
            f0 = *(const float4*)&A[(size_t)gr * 64 + k8];
            f1 = *(const float4*)&A[(size_t)gr * 64 + k8 + 4];
        } else { f0 = make_float4(0, 0, 0, 0); f1 = f0; }
        uint4 hv, lv;
        split8(f0, f1, hv, lv);
        *(uint4*)&sm2[G2_AH + r * G2_LDA + k8] = hv;
        *(uint4*)&sm2[G2_AL + r * G2_LDA + k8] = lv;
    }
#pragma unroll
    for (int i = 0; i < 8; i++) {
        int c = tid + i * 256;
        int n = c >> 3, k8 = (c & 7) * 8;
        *(uint4*)&sm2[G2_BH + n * G2_LDA + k8] = *(const uint4*)&g_w2t_hi[n * 64 + k8];
        *(uint4*)&sm2[G2_BL + n * G2_LDA + k8] = *(const uint4*)&g_w2t_lo[n * 64 + k8];
    }
    __syncthreads();

    float acc[16][4];
#pragma unroll
    for (int i = 0; i < 16; i++)
#pragma unroll
        for (int j = 0; j < 4; j++) acc[i][j] = 0.0f;

#pragma unroll
    for (int ks = 0; ks < 4; ks++) {
        int col0 = ks * 16 + 2 * tig;
        int col1 = col0 + 8;
        int row0 = warpRow + g, row1 = row0 + 8;
        uint32_t ah[4], al[4];
        ah[0] = *(uint32_t*)&sm2[G2_AH + row0 * G2_LDA + col0];
        ah[1] = *(uint32_t*)&sm2[G2_AH + row1 * G2_LDA + col0];
        ah[2] = *(uint32_t*)&sm2[G2_AH + row0 * G2_LDA + col1];
        ah[3] = *(uint32_t*)&sm2[G2_AH + row1 * G2_LDA + col1];
        al[0] = *(uint32_t*)&sm2[G2_AL + row0 * G2_LDA + col0];
        al[1] = *(uint32_t*)&sm2[G2_AL + row1 * G2_LDA + col0];
        al[2] = *(uint32_t*)&sm2[G2_AL + row0 * G2_LDA + col1];
        al[3] = *(uint32_t*)&sm2[G2_AL + row1 * G2_LDA + col1];
#pragma unroll
        for (int nt = 0; nt < 16; nt++) {
            int nr = warpCol + nt * 8 + g;
            uint32_t bh[2], bl[2];
            bh[0] = *(uint32_t*)&sm2[G2_BH + nr * G2_LDA + col0];
            bh[1] = *(uint32_t*)&sm2[G2_BH + nr * G2_LDA + col1];
            bl[0] = *(uint32_t*)&sm2[G2_BL + nr * G2_LDA + col0];
            bl[1] = *(uint32_t*)&sm2[G2_BL + nr * G2_LDA + col1];
            mma16816(acc[nt], ah, bh);
            mma16816(acc[nt], ah, bl);
            mma16816(acc[nt], al, bh);
        }
    }
    int gr0 = rowBase + warpRow + g;
    int gr1 = gr0 + 8;
#pragma unroll
    for (int nt = 0; nt < 16; nt++) {
        int col = warpCol + nt * 8 + 2 * tig;
        float2 bv = *(const float2*)&bias[col];
        if (gr0 < M)
            *(float2*)&C[(size_t)gr0 * 256 + col] = make_float2(acc[nt][0] + bv.x, acc[nt][1] + bv.y);
        if (gr1 < M)
            *(float2*)&C[(size_t)gr1 * 256 + col] = make_float2(acc[nt][2] + bv.x, acc[nt][3] + bv.y);
    }
}

// ---------------------------------------------------------------------------
// CSR aggregation: fp16 gathers (half the L2 traffic), fp32 accumulate
// ---------------------------------------------------------------------------
__global__ void k_agg64(const __half2* __restrict__ h,
                        const float* __restrict__ bias,
                        float* __restrict__ out, int n, int relu) {
    int node = blockIdx.x * 8 + (threadIdx.x >> 5);
    if (node >= n) return;
    int lane = threadIdx.x & 31;
    float dn = g_dinv[node];
    float2 self = __half22float2(h[node * 32 + lane]);
    float ax = self.x * dn * dn;
    float ay = self.y * dn * dn;
    int p = g_off[node], end = g_off[node + 1];
    for (; p + 3 < end; p += 4) {
        int2 e0 = g_edge[p],     e1 = g_edge[p + 1];
        int2 e2 = g_edge[p + 2], e3 = g_edge[p + 3];
        float2 v0 = __half22float2(h[e0.x * 32 + lane]);
        float2 v1 = __half22float2(h[e1.x * 32 + lane]);
        float2 v2 = __half22float2(h[e2.x * 32 + lane]);
        float2 v3 = __half22float2(h[e3.x * 32 + lane]);
        float w0 = __int_as_float(e0.y), w1 = __int_as_float(e1.y);
        float w2 = __int_as_float(e2.y), w3 = __int_as_float(e3.y);
        ax += v0.x * w0 + v1.x * w1 + v2.x * w2 + v3.x * w3;
        ay += v0.y * w0 + v1.y * w1 + v2.y * w2 + v3.y * w3;
    }
    for (; p < end; p++) {
        int2 e = g_edge[p];
        float w = __int_as_float(e.y);
        float2 v = __half22float2(h[e.x * 32 + lane]);
        ax += v.x * w;
        ay += v.y * w;
    }
    if (bias) {
        float2 b = ((const float2*)bias)[lane];
        ax += b.x; ay += b.y;
    }
    if (relu) { ax = fmaxf(ax, 0.0f); ay = fmaxf(ay, 0.0f); }
    ((float2*)out)[node * 32 + lane] = make_float2(ax, ay);
}

// ---------------------------------------------------------------------------
// Fused mid: z (fp32 out), hd (fp16 out), pred (fp32 out)
// ---------------------------------------------------------------------------
__global__ void k_fused_mid(const float* __restrict__ h1,
                            const float* __restrict__ Wef, const float* __restrict__ bef,
                            const float* __restrict__ Wdf, const float* __restrict__ bdf,
                            const float* __restrict__ Wc,  const float* __restrict__ bc,
                            float* __restrict__ z_out, __half2* __restrict__ hd_out,
                            float* __restrict__ pred_out, int n) {
    __shared__ float sWef[64 * 32];
    __shared__ float sWdf[32 * 64];
    __shared__ float sWc[32 * 3];
    __shared__ float sbef[32], sbdf[64], sbc[3];
    __shared__ float sh[16][64];
    __shared__ float sz[16][32];
    int tid = threadIdx.x;  // 256
    for (int i = tid; i < 64 * 32; i += 256) sWef[i] = Wef[i];
    for (int i = tid; i < 32 * 64; i += 256) sWdf[i] = Wdf[i];
    for (int i = tid; i < 32 * 3; i += 256) sWc[i] = Wc[i];
    if (tid < 32) sbef[tid] = bef[tid];
    if (tid < 64) sbdf[tid] = bdf[tid];
    if (tid < 3)  sbc[tid]  = bc[tid];
    int rowBase = blockIdx.x * 16;
    for (int i = tid; i < 16 * 64; i += 256) {
        int r = i >> 6, c = i & 63;
        int gr = rowBase + r;
        sh[r][c] = (gr < n) ? h1[gr * 64 + c] : 0.0f;
    }
    __syncthreads();
    for (int o = tid; o < 512; o += 256) {
        int r = o >> 5, j = o & 31;
        float acc = sbef[j];
#pragma unroll
        for (int k = 0; k < 64; k++) acc += sh[r][k] * sWef[k * 32 + j];
        sz[r][j] = acc;
        int gr = rowBase + r;
        if (gr < n) z_out[gr * 32 + j] = acc;
    }
    __syncthreads();
    // hd: 16 rows x 32 half2 (two j per thread-item)
    for (int o = tid; o < 512; o += 256) {
        int r = o >> 5, j2 = o & 31;
        int j0 = 2 * j2, j1 = j0 + 1;
        float a0 = sbdf[j0], a1 = sbdf[j1];
#pragma unroll
        for (int k = 0; k < 32; k++) {
            float zv = sz[r][k];
            a0 += zv * sWdf[k * 64 + j0];
            a1 += zv * sWdf[k * 64 + j1];
        }
        a0 = fmaxf(a0, 0.0f);
        a1 = fmaxf(a1, 0.0f);
        int gr = rowBase + r;
        if (gr < n) hd_out[(size_t)gr * 32 + j2] = __floats2half2_rn(a0, a1);
    }
    for (int o = tid; o < 48; o += 256) {
        int r = o / 3, j = o % 3;
        float acc = sbc[j];
#pragma unroll
        for (int k = 0; k < 32; k++) acc += sz[r][k] * sWc[k * 3 + j];
        int gr = rowBase + r;
        if (gr < n) pred_out[gr * 3 + j] = acc;
    }
}

// ---------------------------------------------------------------------------
// Host launch: fork CSR chain onto side stream, overlap with wconv+GEMM1
// ---------------------------------------------------------------------------
extern "C" void kernel_launch(void* const* d_in, const int* in_sizes, int n_in,
                              void* d_out, int out_size) {
    const float* x         = (const float*)d_in[0];
    const int*   edge_idx  = (const int*)d_in[1];
    const float* W_enc_gnn = (const float*)d_in[3];
    const float* b_enc_gnn = (const float*)d_in[4];
    const float* W_enc_fc  = (const float*)d_in[5];
    const float* b_enc_fc  = (const float*)d_in[6];
    const float* W_dec_fc  = (const float*)d_in[7];
    const float* b_dec_fc  = (const float*)d_in[8];
    const float* W_dec_gnn = (const float*)d_in[9];
    const float* b_dec_gnn = (const float*)d_in[10];
    const float* W_cond    = (const float*)d_in[11];
    const float* b_cond    = (const float*)d_in[12];

    int N = in_sizes[0] / 256;
    int E = in_sizes[2];
    const int* src = edge_idx;
    const int* dst = edge_idx + E;

    float* out_xrecon = (float*)d_out;
    float* out_z      = out_xrecon + (size_t)N * 256;
    float* out_pred   = out_z + (size_t)N * 32;

    __half2 *p_h1pre, *p_hd;
    float *p_h1, *p_a2;
    int *p_cnt;
    cudaGetSymbolAddress((void**)&p_h1pre, g_h1pre);
    cudaGetSymbolAddress((void**)&p_h1,    g_h1);
    cudaGetSymbolAddress((void**)&p_hd,    g_hd);
    cudaGetSymbolAddress((void**)&p_a2,    g_a2);
    cudaGetSymbolAddress((void**)&p_cnt,   g_cnt);

    // one-time setup (no device memory allocation involved)
    static cudaStream_t sCsr = nullptr;
    static cudaEvent_t evFork = nullptr, evCsrDone = nullptr;
    if (!sCsr) {
        cudaStreamCreateWithFlags(&sCsr, cudaStreamNonBlocking);
        cudaEventCreateWithFlags(&evFork, cudaEventDisableTiming);
        cudaEventCreateWithFlags(&evCsrDone, cudaEventDisableTiming);
        cudaFuncSetAttribute(k_mma_gemm1, cudaFuncAttributeMaxDynamicSharedMemorySize, G1_SMEM);
        cudaFuncSetAttribute(k_mma_gemm2, cudaFuncAttributeMaxDynamicSharedMemorySize, G2_SMEM);
    }

    int nbE  = (E + 255) / 256;
    int nbSc = (N + 1023) / 1024;

    // ---- fork: CSR chain on side stream ----
    cudaEventRecord(evFork, 0);
    cudaStreamWaitEvent(sCsr, evFork, 0);

    cudaMemsetAsync(p_cnt, 0, (size_t)N * sizeof(int), sCsr);
    k_count<<<nbE, 256, 0, sCsr>>>(dst, E);
    k_scan_bsum<<<nbSc, 1024, 0, sCsr>>>(N);
    k_scan_sums<<<1, 64, 0, sCsr>>>(nbSc);
    k_scan_final<<<nbSc, 1024, 0, sCsr>>>(N, E);
    k_fill<<<nbE, 256, 0, sCsr>>>(src, dst, E);
    cudaEventRecord(evCsrDone, sCsr);

    // ---- main stream: weights + GEMM1 (independent of CSR) ----
    k_wconv<<<128, 256>>>(W_enc_gnn, W_dec_gnn);
    k_mma_gemm1<<<(N + 127) / 128, 256, G1_SMEM>>>(x, p_h1pre, N);

    // ---- join: aggregation needs both h1pre and the CSR ----
    cudaStreamWaitEvent(0, evCsrDone, 0);

    k_agg64<<<(N + 7) / 8, 256>>>(p_h1pre, b_enc_gnn, p_h1, N, 1);

    k_fused_mid<<<(N + 15) / 16, 256>>>(p_h1, W_enc_fc, b_enc_fc,
                                        W_dec_fc, b_dec_fc, W_cond, b_cond,
                                        out_z, p_hd, out_pred, N);

    k_agg64<<<(N + 7) / 8, 256>>>(p_hd, (const float*)nullptr, p_a2, N, 0);
    k_mma_gemm2<<<(N + 63) / 64, 256, G2_SMEM>>>(p_a2, b_dec_gnn, out_xrecon, N);
}